// round 14
// baseline (speedup 1.0000x reference)
#include <cuda_runtime.h>
#include <cuda_bf16.h>
#include <math.h>
#include <stdint.h>

constexpr int Bc  = 2;
constexpr int Sc  = 2048;
constexpr int Dc  = 1024;
constexpr int Lc  = 512;
constexpr int Hc  = 8;
constexpr int HDc = 128;
constexpr int Ec  = 8;
constexpr int Fc  = 4096;
constexpr int NT  = Bc * Sc;

// fp32 regions
constexpr size_t OFF_Q     = 0;
constexpr size_t OFF_K     = OFF_Q   + (size_t)NT * Dc;
constexpr size_t OFF_V     = OFF_K   + (size_t)NT * Dc;
constexpr size_t OFF_H     = OFF_V   + (size_t)NT * Dc;
constexpr size_t OFF_MOE   = OFF_H   + (size_t)NT * Dc;
constexpr size_t OFF_WSLOT = OFF_MOE + (size_t)2 * NT * Dc;
constexpr size_t OFF_ELIST = OFF_WSLOT + (size_t)2 * NT;
constexpr size_t OFF_ECNT  = OFF_ELIST + (size_t)Ec * NT;
// u32 plane regions (1 u32 per element pair)
constexpr size_t OFF_XNH   = OFF_ECNT + 64;
constexpr size_t OFF_XNL   = OFF_XNH  + (size_t)NT * (Dc / 2);
constexpr size_t OFF_LATH  = OFF_XNL  + (size_t)NT * (Dc / 2);
constexpr size_t OFF_LATL  = OFF_LATH + (size_t)NT * (Lc / 2);
constexpr size_t OFF_AOH   = OFF_LATL + (size_t)NT * (Lc / 2);
constexpr size_t OFF_AOL   = OFF_AOH  + (size_t)NT * (Dc / 2);
constexpr size_t OFF_HNH   = OFF_AOL  + (size_t)NT * (Dc / 2);
constexpr size_t OFF_HNL   = OFF_HNH  + (size_t)NT * (Dc / 2);
constexpr size_t OFF_ACTH  = OFF_HNL  + (size_t)NT * (Dc / 2);
constexpr size_t OFF_ACTL  = OFF_ACTH + (size_t)2 * NT * (Fc / 2);
constexpr size_t OFF_WQH   = OFF_ACTL + (size_t)2 * NT * (Fc / 2);
constexpr size_t OFF_WQL   = OFF_WQH  + (size_t)(Dc / 2) * Dc;
constexpr size_t OFF_WDKVH = OFF_WQL  + (size_t)(Dc / 2) * Dc;
constexpr size_t OFF_WDKVL = OFF_WDKVH + (size_t)(Dc / 2) * Lc;
constexpr size_t OFF_WUKH  = OFF_WDKVL + (size_t)(Dc / 2) * Lc;
constexpr size_t OFF_WUKL  = OFF_WUKH + (size_t)(Lc / 2) * Dc;
constexpr size_t OFF_WUVH  = OFF_WUKL + (size_t)(Lc / 2) * Dc;
constexpr size_t OFF_WUVL  = OFF_WUVH + (size_t)(Lc / 2) * Dc;
constexpr size_t OFF_WOH   = OFF_WUVL + (size_t)(Lc / 2) * Dc;
constexpr size_t OFF_WOL   = OFF_WOH  + (size_t)(Dc / 2) * Dc;
constexpr size_t OFF_W1H   = OFF_WOL  + (size_t)(Dc / 2) * Dc;
constexpr size_t OFF_W1L   = OFF_W1H  + (size_t)Ec * (Dc / 2) * Fc;
constexpr size_t OFF_W2H   = OFF_W1L  + (size_t)Ec * (Dc / 2) * Fc;
constexpr size_t OFF_W2L   = OFF_W2H  + (size_t)Ec * (Fc / 2) * Dc;
constexpr size_t BUF_TOTAL = OFF_W2L  + (size_t)Ec * (Fc / 2) * Dc;

__device__ float g_buf[BUF_TOTAL];

__global__ void reset_kernel(int* ecount) {
    if (threadIdx.x < Ec) ecount[threadIdx.x] = 0;
}

// split a pair of fp32 into bf16x2 hi + bf16x2 lo (first arg in low half)
__device__ __forceinline__ void split2(float x0, float x1, uint32_t& hi, uint32_t& lo) {
    uint32_t h;
    asm("cvt.rn.bf16x2.f32 %0, %1, %2;" : "=r"(h) : "f"(x1), "f"(x0));
    float h0 = __uint_as_float(h << 16);
    float h1 = __uint_as_float(h & 0xffff0000u);
    uint32_t l;
    asm("cvt.rn.bf16x2.f32 %0, %1, %2;" : "=r"(l) : "f"(x1 - h1), "f"(x0 - h0));
    hi = h; lo = l;
}

__device__ __forceinline__ void mma_bf16(float* d, const uint32_t* a, const uint32_t* b) {
    asm volatile(
        "mma.sync.aligned.m16n8k16.row.col.f32.bf16.bf16.f32 "
        "{%0,%1,%2,%3}, {%4,%5,%6,%7}, {%8,%9}, {%0,%1,%2,%3};"
        : "+f"(d[0]), "+f"(d[1]), "+f"(d[2]), "+f"(d[3])
        : "r"(a[0]), "r"(a[1]), "r"(a[2]), "r"(a[3]), "r"(b[0]), "r"(b[1]));
}

// ---------------------------------------------------------------------------
// Weight pre-split: pairs along K (rows). WH/WL[p][n] = split(W[2p][n], W[2p+1][n])
// ---------------------------------------------------------------------------
__global__ __launch_bounds__(256) void wsplit_kernel(
    const float* __restrict__ W, uint32_t* __restrict__ WH,
    uint32_t* __restrict__ WL, int Kp, int N)
{
    size_t id = (size_t)blockIdx.x * 256 + threadIdx.x;
    size_t total = (size_t)Kp * (N / 4);
    if (id >= total) return;
    int nq = N / 4;
    size_t p  = id / nq;
    int   n4  = (int)(id % nq) * 4;
    float4 a = *(const float4*)(W + (2 * p) * N + n4);
    float4 b = *(const float4*)(W + (2 * p + 1) * N + n4);
    uint32_t h, l;
    uint4 vh, vl;
    split2(a.x, b.x, h, l); vh.x = h; vl.x = l;
    split2(a.y, b.y, h, l); vh.y = h; vl.y = l;
    split2(a.z, b.z, h, l); vh.z = h; vl.z = l;
    split2(a.w, b.w, h, l); vh.w = h; vl.w = l;
    *(uint4*)(WH + p * N + n4) = vh;
    *(uint4*)(WL + p * N + n4) = vl;
}

// ---------------------------------------------------------------------------
// LayerNorm -> hi/lo planes; optional fused MoE gate.
// ---------------------------------------------------------------------------
template <bool GATE>
__global__ __launch_bounds__(256) void ln_kernel(
    const float* __restrict__ x, const float* __restrict__ g,
    const float* __restrict__ b, uint32_t* __restrict__ YH,
    uint32_t* __restrict__ YL,
    const float* __restrict__ Wg, float* __restrict__ wslot,
    int* __restrict__ elist, int* __restrict__ ecount)
{
    int t = blockIdx.x;
    int tid = threadIdx.x;
    const float* xr = x + (size_t)t * Dc;
    float s = 0.f, s2 = 0.f;
    #pragma unroll
    for (int i = tid; i < Dc; i += 256) { float v = xr[i]; s += v; s2 += v * v; }
    __shared__ float sh[2][256];
    __shared__ float gsh[8][Ec];
    sh[0][tid] = s; sh[1][tid] = s2;
    __syncthreads();
    for (int st = 128; st > 0; st >>= 1) {
        if (tid < st) { sh[0][tid] += sh[0][tid + st]; sh[1][tid] += sh[1][tid + st]; }
        __syncthreads();
    }
    float mu   = sh[0][0] * (1.f / Dc);
    float var  = sh[1][0] * (1.f / Dc) - mu * mu;
    float rstd = rsqrtf(var + 1e-5f);
    uint32_t* yh = YH + (size_t)t * (Dc / 2);
    uint32_t* yl = YL + (size_t)t * (Dc / 2);

    float gacc[Ec];
    if (GATE) {
        #pragma unroll
        for (int e = 0; e < Ec; e++) gacc[e] = 0.f;
    }
    #pragma unroll
    for (int i = tid; i < Dc / 2; i += 256) {
        int i0 = 2 * i, i1 = 2 * i + 1;
        float y0 = (xr[i0] - mu) * rstd * g[i0] + b[i0];
        float y1 = (xr[i1] - mu) * rstd * g[i1] + b[i1];
        uint32_t h, l;
        split2(y0, y1, h, l);
        yh[i] = h; yl[i] = l;
        if (GATE) {
            const float* w0 = Wg + (size_t)i0 * Ec;
            const float* w1 = Wg + (size_t)i1 * Ec;
            #pragma unroll
            for (int e = 0; e < Ec; e++)
                gacc[e] = fmaf(y0, w0[e], fmaf(y1, w1[e], gacc[e]));
        }
    }
    if (!GATE) return;

    #pragma unroll
    for (int e = 0; e < Ec; e++)
        #pragma unroll
        for (int m = 16; m >= 1; m >>= 1)
            gacc[e] += __shfl_xor_sync(0xffffffffu, gacc[e], m);
    int warp = tid >> 5, lane = tid & 31;
    if (lane == 0)
        #pragma unroll
        for (int e = 0; e < Ec; e++) gsh[warp][e] = gacc[e];
    __syncthreads();
    if (tid == 0) {
        float lg[Ec];
        #pragma unroll
        for (int e = 0; e < Ec; e++) {
            float v = 0.f;
            #pragma unroll
            for (int w = 0; w < 8; w++) v += gsh[w][e];
            lg[e] = v;
        }
        int e0 = 0; float l0 = lg[0];
        #pragma unroll
        for (int e = 1; e < Ec; e++) if (lg[e] > l0) { l0 = lg[e]; e0 = e; }
        int e1 = -1; float l1 = -3.4e38f;
        #pragma unroll
        for (int e = 0; e < Ec; e++) {
            if (e == e0) continue;
            if (lg[e] > l1) { l1 = lg[e]; e1 = e; }
        }
        float t1 = expf(l1 - l0);
        float w0 = 1.f / (1.f + t1);
        float w1 = t1 / (1.f + t1);
        wslot[2 * t]     = w0;
        wslot[2 * t + 1] = w1;
        int p0 = atomicAdd(&ecount[e0], 1);
        elist[e0 * NT + p0] = 2 * t;
        int p1 = atomicAdd(&ecount[e1], 1);
        elist[e1 * NT + p1] = 2 * t + 1;
    }
}

// ---------------------------------------------------------------------------
// tgemm v5: operands are pre-split global hi/lo planes. Loader is pure
// LDG.128 -> STS.128. 128x128 tile, BK=16, double-buffered, ONE barrier/ktile.
// 8 warps 2(M) x 4(N), warp tile 64x32. EPI: 0 none, 1 +resid, 2 silu,
// 3 *wslot. GATHER via elist. Output fp32 (C) or planes (CH/CL non-null).
// Optional second op via blockIdx.z==1 (non-gather).
// ---------------------------------------------------------------------------
constexpr int PA = 12;
constexpr int PB = 136;

template <int EPI, bool GATHER>
__global__ __launch_bounds__(256, 2) void tgemm_kernel(
    const uint32_t* __restrict__ AH, const uint32_t* __restrict__ AL,
    const uint32_t* __restrict__ BH, const uint32_t* __restrict__ BL,
    const float* __restrict__ resid,
    float* __restrict__ C, uint32_t* __restrict__ CH, uint32_t* __restrict__ CL,
    int K, int N,
    const int* __restrict__ elist, const int* __restrict__ ecount,
    const float* __restrict__ wslot, int ashift, size_t bExpertStride,
    const uint32_t* __restrict__ B2H, const uint32_t* __restrict__ B2L,
    float* __restrict__ C2, uint32_t* __restrict__ C2H, uint32_t* __restrict__ C2L,
    int N2)
{
    __shared__ uint32_t Ahi[2][128][PA], Alo[2][128][PA];
    __shared__ uint32_t Bhi[2][8][PB],   Blo[2][8][PB];

    const int tid  = threadIdx.x;
    const int warp = tid >> 5;
    const int lane = tid & 31;
    const int wy = warp & 1;
    const int wx = warp >> 1;
    const int mW = wy * 64;
    const int nW = wx * 32;
    const int g  = lane >> 2;
    const int lm = lane & 3;

    const int n0 = blockIdx.x * 128;
    const int KP = K >> 1;

    int e = 0, cnt = 0, rt = 0, m0 = 0;
    const uint32_t* BHb = BH;
    const uint32_t* BLb = BL;
    float* Cf = C;
    uint32_t* CHp = CH;
    uint32_t* CLp = CL;
    int Nn = N;
    if (GATHER) {
        e = blockIdx.z;
        cnt = ecount[e];
        rt = blockIdx.y * 128;
        if (rt >= cnt) return;
        BHb = BH + (size_t)e * bExpertStride;
        BLb = BL + (size_t)e * bExpertStride;
    } else {
        m0 = blockIdx.y * 128;
        if (B2H != nullptr && blockIdx.z == 1) {
            BHb = B2H; BLb = B2L; Cf = C2; CHp = C2H; CLp = C2L; Nn = N2;
            if (n0 >= Nn) return;
        }
    }

    const int arow = tid >> 1;
    const int akp0 = (tid & 1) * 4;
    const int bkp  = tid >> 5;
    const int bn   = (tid & 31) * 4;

    size_t aoff;
    bool avalid = true;
    if (GATHER) {
        int gr = rt + arow;
        avalid = gr < cnt;
        int slot = avalid ? elist[e * NT + gr] : 0;
        aoff = (size_t)(slot >> ashift) * KP + akp0;
    } else {
        aoff = (size_t)(m0 + arow) * KP + akp0;
    }

    float acc[4][4][4];
    #pragma unroll
    for (int i = 0; i < 4; i++)
        #pragma unroll
        for (int j = 0; j < 4; j++)
            #pragma unroll
            for (int c = 0; c < 4; c++) acc[i][j][c] = 0.f;

    const int KT = K >> 4;     // kpairs per ktile = 8
    const uint4 uz = make_uint4(0, 0, 0, 0);

    // stage tile 0
    uint4 aH = avalid ? *(const uint4*)(AH + aoff) : uz;
    uint4 aL = avalid ? *(const uint4*)(AL + aoff) : uz;
    uint4 bHs = *(const uint4*)(BHb + (size_t)bkp * Nn + n0 + bn);
    uint4 bLs = *(const uint4*)(BLb + (size_t)bkp * Nn + n0 + bn);

    for (int kt = 0; kt < KT; kt++) {
        const int cb = kt & 1;
        *(uint4*)&Ahi[cb][arow][akp0] = aH;
        *(uint4*)&Alo[cb][arow][akp0] = aL;
        *(uint4*)&Bhi[cb][bkp][bn]    = bHs;
        *(uint4*)&Blo[cb][bkp][bn]    = bLs;
        __syncthreads();

        if (kt + 1 < KT) {
            size_t ka = aoff + (size_t)(kt + 1) * 8;
            aH = avalid ? *(const uint4*)(AH + ka) : uz;
            aL = avalid ? *(const uint4*)(AL + ka) : uz;
            size_t kb = (size_t)((kt + 1) * 8 + bkp) * Nn + n0 + bn;
            bHs = *(const uint4*)(BHb + kb);
            bLs = *(const uint4*)(BLb + kb);
        }

        uint32_t ahi[4][4], alo[4][4];
        #pragma unroll
        for (int mi = 0; mi < 4; mi++) {
            int r = mW + mi * 16 + g;
            ahi[mi][0] = Ahi[cb][r    ][lm];
            ahi[mi][1] = Ahi[cb][r + 8][lm];
            ahi[mi][2] = Ahi[cb][r    ][lm + 4];
            ahi[mi][3] = Ahi[cb][r + 8][lm + 4];
            alo[mi][0] = Alo[cb][r    ][lm];
            alo[mi][1] = Alo[cb][r + 8][lm];
            alo[mi][2] = Alo[cb][r    ][lm + 4];
            alo[mi][3] = Alo[cb][r + 8][lm + 4];
        }
        #pragma unroll
        for (int ni = 0; ni < 4; ni++) {
            int c = nW + ni * 8 + g;
            uint32_t bhi[2], blo[2];
            bhi[0] = Bhi[cb][lm    ][c];
            bhi[1] = Bhi[cb][lm + 4][c];
            blo[0] = Blo[cb][lm    ][c];
            blo[1] = Blo[cb][lm + 4][c];
            #pragma unroll
            for (int mi = 0; mi < 4; mi++) {
                mma_bf16(acc[mi][ni], ahi[mi], bhi);
                mma_bf16(acc[mi][ni], ahi[mi], blo);
                mma_bf16(acc[mi][ni], alo[mi], bhi);
            }
        }
    }

    #pragma unroll
    for (int mi = 0; mi < 4; mi++) {
        int r0 = mW + mi * 16 + g;
        int r1 = r0 + 8;
        size_t row0, row1;
        bool v0 = true, v1 = true;
        float w0 = 1.f, w1 = 1.f;
        if (GATHER) {
            int g0 = rt + r0, g1 = rt + r1;
            v0 = g0 < cnt; v1 = g1 < cnt;
            int s0 = v0 ? elist[e * NT + g0] : 0;
            int s1 = v1 ? elist[e * NT + g1] : 0;
            row0 = (size_t)s0;
            row1 = (size_t)s1;
            if (EPI == 3) { w0 = v0 ? wslot[s0] : 0.f; w1 = v1 ? wslot[s1] : 0.f; }
        } else {
            row0 = (size_t)(m0 + r0);
            row1 = (size_t)(m0 + r1);
        }
        #pragma unroll
        for (int ni = 0; ni < 4; ni++) {
            int col = n0 + nW + ni * 8 + 2 * lm;
            float x0 = acc[mi][ni][0], x1 = acc[mi][ni][1];
            float x2 = acc[mi][ni][2], x3 = acc[mi][ni][3];
            if (EPI == 1) {
                const float* rp0 = resid + row0 * Nn + col;
                const float* rp1 = resid + row1 * Nn + col;
                x0 += rp0[0]; x1 += rp0[1];
                x2 += rp1[0]; x3 += rp1[1];
            } else if (EPI == 2) {
                x0 = x0 / (1.f + __expf(-x0));
                x1 = x1 / (1.f + __expf(-x1));
                x2 = x2 / (1.f + __expf(-x2));
                x3 = x3 / (1.f + __expf(-x3));
            } else if (EPI == 3) {
                x0 *= w0; x1 *= w0; x2 *= w1; x3 *= w1;
            }
            if (CHp) {
                uint32_t h, l;
                if (v0) {
                    split2(x0, x1, h, l);
                    CHp[row0 * (Nn / 2) + (col >> 1)] = h;
                    CLp[row0 * (Nn / 2) + (col >> 1)] = l;
                }
                if (v1) {
                    split2(x2, x3, h, l);
                    CHp[row1 * (Nn / 2) + (col >> 1)] = h;
                    CLp[row1 * (Nn / 2) + (col >> 1)] = l;
                }
            } else {
                if (v0) *(float2*)&Cf[row0 * Nn + col] = make_float2(x0, x1);
                if (v1) *(float2*)&Cf[row1 * Nn + col] = make_float2(x2, x3);
            }
        }
    }
}

__global__ __launch_bounds__(256) void rope_kernel(
    float* __restrict__ q, float* __restrict__ k, const float* __restrict__ freqs)
{
    int p = blockIdx.x * 256 + threadIdx.x;
    int t = p >> 9;
    int r = p & 511;
    int hh = r >> 6;
    int i  = r & 63;
    int s  = t & (Sc - 1);
    float f = freqs[s * 64 + i];
    float c = cosf(f), sn = sinf(f);
    size_t base = (size_t)t * Dc + hh * HDc + 2 * i;
    float e = q[base], o = q[base + 1];
    q[base] = e * c - o * sn; q[base + 1] = e * sn + o * c;
    e = k[base]; o = k[base + 1];
    k[base] = e * c - o * sn; k[base + 1] = e * sn + o * c;
}

// ---------------------------------------------------------------------------
// Flash attention (round-10 core); output written as hi/lo planes.
// ---------------------------------------------------------------------------
constexpr int QKP = 68;
constexpr int VP  = 136;
constexpr int PP  = 36;
constexpr int FQH = 0;
constexpr int FQL = FQH + 64 * QKP;
constexpr int FKH = FQL + 64 * QKP;
constexpr int FKL = FKH + 64 * QKP;
constexpr int FVH = FKL + 64 * QKP;
constexpr int FVL = FVH + 32 * VP;
constexpr int FPH = FVL + 32 * VP;
constexpr int FPL = FPH + 64 * PP;
constexpr int FRM = FPL + 64 * PP;
constexpr int FRS = FRM + 128;
constexpr int FLASH_SMEM = (FRS + 128) * 4;

__global__ __launch_bounds__(256) void flash_tc_kernel(
    const float* __restrict__ q, const float* __restrict__ k,
    const float* __restrict__ v, uint32_t* __restrict__ aoH,
    uint32_t* __restrict__ aoL)
{
    extern __shared__ uint32_t smu[];
    uint32_t* QH = smu + FQH;
    uint32_t* QL = smu + FQL;
    uint32_t* KH = smu + FKH;
    uint32_t* KL = smu + FKL;
    uint32_t* VH = smu + FVH;
    uint32_t* VL = smu + FVL;
    uint32_t* PH = smu + FPH;
    uint32_t* PL = smu + FPL;
    float* RM = (float*)(smu + FRM);
    float* RS = (float*)(smu + FRS);

    const int tid  = threadIdx.x;
    const int warp = tid >> 5;
    const int lane = tid & 31;
    const int wy = warp >> 1;
    const int wx = warp & 1;
    const int g  = lane >> 2;
    const int lm = lane & 3;

    const int qb = (gridDim.x - 1) - blockIdx.x;
    const int hh = blockIdx.y, b = blockIdx.z;
    const size_t qbase = ((size_t)(b * Sc + qb * 64)) * Dc + hh * HDc;
    const float scale = 0.08838834764831845f;

    const int row0 = wy * 16 + g;
    const int row1 = row0 + 8;

    #pragma unroll
    for (int i = 0; i < 8; i++) {
        int li = tid + i * 256;
        int r = li >> 5, c = (li & 31) * 4;
        float4 val = *(const float4*)(q + qbase + (size_t)r * Dc + c);
        uint32_t h, l;
        split2(val.x * scale, val.y * scale, h, l);
        QH[r * QKP + c / 2] = h; QL[r * QKP + c / 2] = l;
        split2(val.z * scale, val.w * scale, h, l);
        QH[r * QKP + c / 2 + 1] = h; QL[r * QKP + c / 2 + 1] = l;
    }

    float oacc[8][4];
    #pragma unroll
    for (int ni = 0; ni < 8; ni++)
        #pragma unroll
        for (int c = 0; c < 4; c++) oacc[ni][c] = 0.f;
    float m0s = -1e30f, m1s = -1e30f, l0s = 0.f, l1s = 0.f;

    for (int kb = 0; kb <= qb; kb++) {
        const size_t kbase = ((size_t)(b * Sc + kb * 64)) * Dc + hh * HDc;
        #pragma unroll
        for (int i = 0; i < 8; i++) {
            int li = tid + i * 256;
            int r = li >> 5, c = (li & 31) * 4;
            float4 kv = *(const float4*)(k + kbase + (size_t)r * Dc + c);
            uint32_t h, l;
            split2(kv.x, kv.y, h, l);
            KH[r * QKP + c / 2] = h; KL[r * QKP + c / 2] = l;
            split2(kv.z, kv.w, h, l);
            KH[r * QKP + c / 2 + 1] = h; KL[r * QKP + c / 2 + 1] = l;
        }
        #pragma unroll
        for (int i = 0; i < 4; i++) {
            int li = tid + i * 256;
            int j = li >> 5, c = (li & 31) * 4;
            float4 v0 = *(const float4*)(v + kbase + (size_t)(2 * j) * Dc + c);
            float4 v1 = *(const float4*)(v + kbase + (size_t)(2 * j + 1) * Dc + c);
            uint32_t h, l;
            uint4 vh, vl;
            split2(v0.x, v1.x, h, l); vh.x = h; vl.x = l;
            split2(v0.y, v1.y, h, l); vh.y = h; vl.y = l;
            split2(v0.z, v1.z, h, l); vh.z = h; vl.z = l;
            split2(v0.w, v1.w, h, l); vh.w = h; vl.w = l;
            *(uint4*)&VH[j * VP + c] = vh;
            *(uint4*)&VL[j * VP + c] = vl;
        }
        __syncthreads();

        float sacc[4][4];
        #pragma unroll
        for (int ni = 0; ni < 4; ni++)
            #pragma unroll
            for (int c = 0; c < 4; c++) sacc[ni][c] = 0.f;

        #pragma unroll
        for (int ks = 0; ks < 8; ks++) {
            int kpb = ks * 8;
            uint32_t ahi[4], alo[4];
            ahi[0] = QH[row0 * QKP + kpb + lm];
            ahi[1] = QH[row1 * QKP + kpb + lm];
            ahi[2] = QH[row0 * QKP + kpb + lm + 4];
            ahi[3] = QH[row1 * QKP + kpb + lm + 4];
            alo[0] = QL[row0 * QKP + kpb + lm];
            alo[1] = QL[row1 * QKP + kpb + lm];
            alo[2] = QL[row0 * QKP + kpb + lm + 4];
            alo[3] = QL[row1 * QKP + kpb + lm + 4];
            #pragma unroll
            for (int ni = 0; ni < 4; ni++) {
                int ck = wx * 32 + ni * 8 + g;
                uint32_t bhi[2], blo[2];
                bhi[0] = KH[ck * QKP + kpb + lm];
                bhi[1] = KH[ck * QKP + kpb + lm + 4];
                blo[0] = KL[ck * QKP + kpb + lm];
                blo[1] = KL[ck * QKP + kpb + lm + 4];
                mma_bf16(sacc[ni], ahi, bhi);
                mma_bf16(sacc[ni], ahi, blo);
                mma_bf16(sacc[ni], alo, bhi);
            }
        }

        if (kb == qb) {
            int qa0 = qb * 64 + row0;
            int qa1 = qb * 64 + row1;
            #pragma unroll
            for (int ni = 0; ni < 4; ni++) {
                int ka = kb * 64 + wx * 32 + ni * 8 + 2 * lm;
                if (ka     > qa0) sacc[ni][0] = -1e30f;
                if (ka + 1 > qa0) sacc[ni][1] = -1e30f;
                if (ka     > qa1) sacc[ni][2] = -1e30f;
                if (ka + 1 > qa1) sacc[ni][3] = -1e30f;
            }
        }

        float rm0 = -1e30f, rm1 = -1e30f;
        #pragma unroll
        for (int ni = 0; ni < 4; ni++) {
            rm0 = fmaxf(rm0, fmaxf(sacc[ni][0], sacc[ni][1]));
            rm1 = fmaxf(rm1, fmaxf(sacc[ni][2], sacc[ni][3]));
        }
        rm0 = fmaxf(rm0, __shfl_xor_sync(0xffffffffu, rm0, 1));
        rm0 = fmaxf(rm0, __shfl_xor_sync(0xffffffffu, rm0, 2));
        rm1 = fmaxf(rm1, __shfl_xor_sync(0xffffffffu, rm1, 1));
        rm1 = fmaxf(rm1, __shfl_xor_sync(0xffffffffu, rm1, 2));
        if (lm == 0) {
            RM[row0 * 2 + wx] = rm0;
            RM[row1 * 2 + wx] = rm1;
        }
        __syncthreads();

        float mn0 = fmaxf(m0s, fmaxf(RM[row0 * 2], RM[row0 * 2 + 1]));
        float mn1 = fmaxf(m1s, fmaxf(RM[row1 * 2], RM[row1 * 2 + 1]));

        float ps0 = 0.f, ps1 = 0.f;
        #pragma unroll
        for (int ni = 0; ni < 4; ni++) {
            float p0 = __expf(sacc[ni][0] - mn0);
            float p1 = __expf(sacc[ni][1] - mn0);
            float p2 = __expf(sacc[ni][2] - mn1);
            float p3 = __expf(sacc[ni][3] - mn1);
            ps0 += p0 + p1; ps1 += p2 + p3;
            int kpw = wx * 16 + ni * 4 + lm;
            uint32_t h, l;
            split2(p0, p1, h, l);
            PH[row0 * PP + kpw] = h; PL[row0 * PP + kpw] = l;
            split2(p2, p3, h, l);
            PH[row1 * PP + kpw] = h; PL[row1 * PP + kpw] = l;
        }
        ps0 += __shfl_xor_sync(0xffffffffu, ps0, 1);
        ps0 += __shfl_xor_sync(0xffffffffu, ps0, 2);
        ps1 += __shfl_xor_sync(0xffffffffu, ps1, 1);
        ps1 += __shfl_xor_sync(0xffffffffu, ps1, 2);
        if (lm == 0) {
            RS[row0 * 2 + wx] = ps0;
            RS[row1 * 2 + wx] = ps1;
        }
        __syncthreads();

        float sc0 = __expf(m0s - mn0);
        float sc1 = __expf(m1s - mn1);
        l0s = l0s * sc0 + RS[row0 * 2] + RS[row0 * 2 + 1];
        l1s = l1s * sc1 + RS[row1 * 2] + RS[row1 * 2 + 1];
        m0s = mn0; m1s = mn1;
        #pragma unroll
        for (int ni = 0; ni < 8; ni++) {
            oacc[ni][0] *= sc0; oacc[ni][1] *= sc0;
            oacc[ni][2] *= sc1; oacc[ni][3] *= sc1;
        }

        #pragma unroll
        for (int ks = 0; ks < 4; ks++) {
            int kpb = ks * 8;
            uint32_t ahi[4], alo[4];
            ahi[0] = PH[row0 * PP + kpb + lm];
            ahi[1] = PH[row1 * PP + kpb + lm];
            ahi[2] = PH[row0 * PP + kpb + lm + 4];
            ahi[3] = PH[row1 * PP + kpb + lm + 4];
            alo[0] = PL[row0 * PP + kpb + lm];
            alo[1] = PL[row1 * PP + kpb + lm];
            alo[2] = PL[row0 * PP + kpb + lm + 4];
            alo[3] = PL[row1 * PP + kpb + lm + 4];
            #pragma unroll
            for (int ni = 0; ni < 8; ni++) {
                int vc = wx * 64 + ni * 8 + g;
                uint32_t bhi[2], blo[2];
                bhi[0] = VH[(kpb + lm)     * VP + vc];
                bhi[1] = VH[(kpb + lm + 4) * VP + vc];
                blo[0] = VL[(kpb + lm)     * VP + vc];
                blo[1] = VL[(kpb + lm + 4) * VP + vc];
                mma_bf16(oacc[ni], ahi, bhi);
                mma_bf16(oacc[ni], ahi, blo);
                mma_bf16(oacc[ni], alo, bhi);
            }
        }
        __syncthreads();
    }

    float inv0 = 1.f / l0s;
    float inv1 = 1.f / l1s;
    const size_t pbase = qbase >> 1;   // plane offset (element pairs)
    #pragma unroll
    for (int ni = 0; ni < 8; ni++) {
        int col = wx * 64 + ni * 8 + 2 * lm;
        uint32_t h, l;
        split2(oacc[ni][0] * inv0, oacc[ni][1] * inv0, h, l);
        aoH[pbase + (size_t)row0 * (Dc / 2) + (col >> 1)] = h;
        aoL[pbase + (size_t)row0 * (Dc / 2) + (col >> 1)] = l;
        split2(oacc[ni][2] * inv1, oacc[ni][3] * inv1, h, l);
        aoH[pbase + (size_t)row1 * (Dc / 2) + (col >> 1)] = h;
        aoL[pbase + (size_t)row1 * (Dc / 2) + (col >> 1)] = l;
    }
}

__global__ __launch_bounds__(256) void combine_kernel(
    const float* __restrict__ h, const float* __restrict__ moeout,
    float* __restrict__ out)
{
    size_t i = (size_t)blockIdx.x * 256 + threadIdx.x;
    size_t t = i >> 10, d = i & 1023;
    out[i] = h[i] + moeout[(2 * t) * (size_t)Dc + d]
                  + moeout[(2 * t + 1) * (size_t)Dc + d];
}

extern "C" void kernel_launch(void* const* d_in, const int* in_sizes, int n_in,
                              void* d_out, int out_size)
{
    const float* x     = (const float*)d_in[0];
    const float* freqs = (const float*)d_in[1];
    const float* g1    = (const float*)d_in[2];
    const float* b1    = (const float*)d_in[3];
    const float* g2    = (const float*)d_in[4];
    const float* b2    = (const float*)d_in[5];
    const float* Wq    = (const float*)d_in[6];
    const float* Wdkv  = (const float*)d_in[7];
    const float* Wuk   = (const float*)d_in[8];
    const float* Wuv   = (const float*)d_in[9];
    const float* Wo    = (const float*)d_in[10];
    const float* Wg    = (const float*)d_in[11];
    const float* W1    = (const float*)d_in[12];
    const float* W2    = (const float*)d_in[13];
    float* out = (float*)d_out;

    void* bufp = nullptr;
    cudaGetSymbolAddress(&bufp, g_buf);
    float* buf   = (float*)bufp;
    float* qb_   = buf + OFF_Q;
    float* kb_   = buf + OFF_K;
    float* vb_   = buf + OFF_V;
    float* h     = buf + OFF_H;
    float* moeo  = buf + OFF_MOE;
    float* wslot = buf + OFF_WSLOT;
    int*   elist = (int*)(buf + OFF_ELIST);
    int*   ecnt  = (int*)(buf + OFF_ECNT);
    uint32_t* ub = (uint32_t*)bufp;
    uint32_t* xnH  = ub + OFF_XNH;
    uint32_t* xnL  = ub + OFF_XNL;
    uint32_t* latH = ub + OFF_LATH;
    uint32_t* latL = ub + OFF_LATL;
    uint32_t* aoH  = ub + OFF_AOH;
    uint32_t* aoL  = ub + OFF_AOL;
    uint32_t* hnH  = ub + OFF_HNH;
    uint32_t* hnL  = ub + OFF_HNL;
    uint32_t* actH = ub + OFF_ACTH;
    uint32_t* actL = ub + OFF_ACTL;
    uint32_t* wqH  = ub + OFF_WQH;
    uint32_t* wqL  = ub + OFF_WQL;
    uint32_t* wdH  = ub + OFF_WDKVH;
    uint32_t* wdL  = ub + OFF_WDKVL;
    uint32_t* wkH  = ub + OFF_WUKH;
    uint32_t* wkL  = ub + OFF_WUKL;
    uint32_t* wvH  = ub + OFF_WUVH;
    uint32_t* wvL  = ub + OFF_WUVL;
    uint32_t* woH  = ub + OFF_WOH;
    uint32_t* woL  = ub + OFF_WOL;
    uint32_t* w1H  = ub + OFF_W1H;
    uint32_t* w1L  = ub + OFF_W1L;
    uint32_t* w2H  = ub + OFF_W2H;
    uint32_t* w2L  = ub + OFF_W2L;

    cudaFuncSetAttribute(flash_tc_kernel,
                         cudaFuncAttributeMaxDynamicSharedMemorySize, FLASH_SMEM);

    reset_kernel<<<1, 32>>>(ecnt);

    // weight pre-split
    auto wsgrid = [](size_t kp, size_t n) {
        return (unsigned)((kp * (n / 4) + 255) / 256);
    };
    wsplit_kernel<<<wsgrid(512, 1024), 256>>>(Wq,   wqH, wqL, 512, 1024);
    wsplit_kernel<<<wsgrid(512, 512),  256>>>(Wdkv, wdH, wdL, 512, 512);
    wsplit_kernel<<<wsgrid(256, 1024), 256>>>(Wuk,  wkH, wkL, 256, 1024);
    wsplit_kernel<<<wsgrid(256, 1024), 256>>>(Wuv,  wvH, wvL, 256, 1024);
    wsplit_kernel<<<wsgrid(512, 1024), 256>>>(Wo,   woH, woL, 512, 1024);
    wsplit_kernel<<<wsgrid(4096, 4096), 256>>>(W1,  w1H, w1L, 4096, 4096);
    wsplit_kernel<<<wsgrid(16384, 1024), 256>>>(W2, w2H, w2L, 16384, 1024);

    ln_kernel<false><<<NT, 256>>>(x, g1, b1, xnH, xnL,
                                  nullptr, nullptr, nullptr, nullptr);

    // fused Wq (z=0 -> q fp32) + Wdkv (z=1 -> lat planes)
    tgemm_kernel<0, false><<<dim3(Dc / 128, NT / 128, 2), 256>>>(
        xnH, xnL, wqH, wqL, nullptr, qb_, nullptr, nullptr, Dc, Dc,
        nullptr, nullptr, nullptr, 0, 0,
        wdH, wdL, nullptr, latH, latL, Lc);
    // fused Wuk (z=0 -> k fp32) + Wuv (z=1 -> v fp32)
    tgemm_kernel<0, false><<<dim3(Dc / 128, NT / 128, 2), 256>>>(
        latH, latL, wkH, wkL, nullptr, kb_, nullptr, nullptr, Lc, Dc,
        nullptr, nullptr, nullptr, 0, 0,
        wvH, wvL, vb_, nullptr, nullptr, Dc);

    rope_kernel<<<(NT * (Dc / 2)) / 256, 256>>>(qb_, kb_, freqs);

    flash_tc_kernel<<<dim3(Sc / 64, Hc, Bc), 256, FLASH_SMEM>>>(
        qb_, kb_, vb_, aoH, aoL);

    // Wo: A = ao planes, +resid x -> h fp32
    tgemm_kernel<1, false><<<dim3(Dc / 128, NT / 128), 256>>>(
        aoH, aoL, woH, woL, x, h, nullptr, nullptr, Dc, Dc,
        nullptr, nullptr, nullptr, 0, 0,
        nullptr, nullptr, nullptr, nullptr, nullptr, 0);

    // second LN + fused gate -> hn planes
    ln_kernel<true><<<NT, 256>>>(h, g2, b2, hnH, hnL, Wg, wslot, elist, ecnt);

    // MoE gemm1: A = hn planes (slot>>1), silu -> act planes
    tgemm_kernel<2, true><<<dim3(Fc / 128, NT / 128, Ec), 256>>>(
        hnH, hnL, w1H, w1L, nullptr, nullptr, actH, actL, Dc, Fc,
        elist, ecnt, nullptr, 1, (size_t)(Dc / 2) * Fc,
        nullptr, nullptr, nullptr, nullptr, nullptr, 0);
    // MoE gemm2: A = act planes (slot), *wslot -> moeo fp32
    tgemm_kernel<3, true><<<dim3(Dc / 128, NT / 128, Ec), 256>>>(
        actH, actL, w2H, w2L, nullptr, moeo, nullptr, nullptr, Fc, Dc,
        elist, ecnt, wslot, 0, (size_t)(Fc / 2) * Dc,
        nullptr, nullptr, nullptr, nullptr, nullptr, 0);

    combine_kernel<<<(NT * Dc) / 256, 256>>>(h, moeo, out);
}

// round 15
// speedup vs baseline: 1.1162x; 1.1162x over previous
#include <cuda_runtime.h>
#include <cuda_bf16.h>
#include <math.h>
#include <stdint.h>

constexpr int Bc  = 2;
constexpr int Sc  = 2048;
constexpr int Dc  = 1024;
constexpr int Lc  = 512;
constexpr int Hc  = 8;
constexpr int HDc = 128;
constexpr int Ec  = 8;
constexpr int Fc  = 4096;
constexpr int NT  = Bc * Sc;

// fp32 regions
constexpr size_t OFF_Q     = 0;
constexpr size_t OFF_K     = OFF_Q   + (size_t)NT * Dc;
constexpr size_t OFF_V     = OFF_K   + (size_t)NT * Dc;
constexpr size_t OFF_H     = OFF_V   + (size_t)NT * Dc;
constexpr size_t OFF_MOE   = OFF_H   + (size_t)NT * Dc;
constexpr size_t OFF_WSLOT = OFF_MOE + (size_t)2 * NT * Dc;
constexpr size_t OFF_ELIST = OFF_WSLOT + (size_t)2 * NT;
constexpr size_t OFF_ECNT  = OFF_ELIST + (size_t)Ec * NT;
// u32 plane regions (1 u32 per element pair)
constexpr size_t OFF_XNH   = OFF_ECNT + 64;
constexpr size_t OFF_XNL   = OFF_XNH  + (size_t)NT * (Dc / 2);
constexpr size_t OFF_LATH  = OFF_XNL  + (size_t)NT * (Dc / 2);
constexpr size_t OFF_LATL  = OFF_LATH + (size_t)NT * (Lc / 2);
constexpr size_t OFF_AOH   = OFF_LATL + (size_t)NT * (Lc / 2);
constexpr size_t OFF_AOL   = OFF_AOH  + (size_t)NT * (Dc / 2);
constexpr size_t OFF_HNH   = OFF_AOL  + (size_t)NT * (Dc / 2);
constexpr size_t OFF_HNL   = OFF_HNH  + (size_t)NT * (Dc / 2);
constexpr size_t OFF_ACTH  = OFF_HNL  + (size_t)NT * (Dc / 2);
constexpr size_t OFF_ACTL  = OFF_ACTH + (size_t)2 * NT * (Fc / 2);
constexpr size_t BUF_TOTAL = OFF_ACTL + (size_t)2 * NT * (Fc / 2);

__device__ float g_buf[BUF_TOTAL];

__global__ void reset_kernel(int* ecount) {
    if (threadIdx.x < Ec) ecount[threadIdx.x] = 0;
}

// split a pair of fp32 into bf16x2 hi + bf16x2 lo (first arg in low half)
__device__ __forceinline__ void split2(float x0, float x1, uint32_t& hi, uint32_t& lo) {
    uint32_t h;
    asm("cvt.rn.bf16x2.f32 %0, %1, %2;" : "=r"(h) : "f"(x1), "f"(x0));
    float h0 = __uint_as_float(h << 16);
    float h1 = __uint_as_float(h & 0xffff0000u);
    uint32_t l;
    asm("cvt.rn.bf16x2.f32 %0, %1, %2;" : "=r"(l) : "f"(x1 - h1), "f"(x0 - h0));
    hi = h; lo = l;
}

__device__ __forceinline__ void mma_bf16(float* d, const uint32_t* a, const uint32_t* b) {
    asm volatile(
        "mma.sync.aligned.m16n8k16.row.col.f32.bf16.bf16.f32 "
        "{%0,%1,%2,%3}, {%4,%5,%6,%7}, {%8,%9}, {%0,%1,%2,%3};"
        : "+f"(d[0]), "+f"(d[1]), "+f"(d[2]), "+f"(d[3])
        : "r"(a[0]), "r"(a[1]), "r"(a[2]), "r"(a[3]), "r"(b[0]), "r"(b[1]));
}

// ---------------------------------------------------------------------------
// LayerNorm -> hi/lo planes; optional fused MoE gate. (round-14, passing)
// ---------------------------------------------------------------------------
template <bool GATE>
__global__ __launch_bounds__(256) void ln_kernel(
    const float* __restrict__ x, const float* __restrict__ g,
    const float* __restrict__ b, uint32_t* __restrict__ YH,
    uint32_t* __restrict__ YL,
    const float* __restrict__ Wg, float* __restrict__ wslot,
    int* __restrict__ elist, int* __restrict__ ecount)
{
    int t = blockIdx.x;
    int tid = threadIdx.x;
    const float* xr = x + (size_t)t * Dc;
    float s = 0.f, s2 = 0.f;
    #pragma unroll
    for (int i = tid; i < Dc; i += 256) { float v = xr[i]; s += v; s2 += v * v; }
    __shared__ float sh[2][256];
    __shared__ float gsh[8][Ec];
    sh[0][tid] = s; sh[1][tid] = s2;
    __syncthreads();
    for (int st = 128; st > 0; st >>= 1) {
        if (tid < st) { sh[0][tid] += sh[0][tid + st]; sh[1][tid] += sh[1][tid + st]; }
        __syncthreads();
    }
    float mu   = sh[0][0] * (1.f / Dc);
    float var  = sh[1][0] * (1.f / Dc) - mu * mu;
    float rstd = rsqrtf(var + 1e-5f);
    uint32_t* yh = YH + (size_t)t * (Dc / 2);
    uint32_t* yl = YL + (size_t)t * (Dc / 2);

    float gacc[Ec];
    if (GATE) {
        #pragma unroll
        for (int e = 0; e < Ec; e++) gacc[e] = 0.f;
    }
    #pragma unroll
    for (int i = tid; i < Dc / 2; i += 256) {
        int i0 = 2 * i, i1 = 2 * i + 1;
        float y0 = (xr[i0] - mu) * rstd * g[i0] + b[i0];
        float y1 = (xr[i1] - mu) * rstd * g[i1] + b[i1];
        uint32_t h, l;
        split2(y0, y1, h, l);
        yh[i] = h; yl[i] = l;
        if (GATE) {
            const float* w0 = Wg + (size_t)i0 * Ec;
            const float* w1 = Wg + (size_t)i1 * Ec;
            #pragma unroll
            for (int e = 0; e < Ec; e++)
                gacc[e] = fmaf(y0, w0[e], fmaf(y1, w1[e], gacc[e]));
        }
    }
    if (!GATE) return;

    #pragma unroll
    for (int e = 0; e < Ec; e++)
        #pragma unroll
        for (int m = 16; m >= 1; m >>= 1)
            gacc[e] += __shfl_xor_sync(0xffffffffu, gacc[e], m);
    int warp = tid >> 5, lane = tid & 31;
    if (lane == 0)
        #pragma unroll
        for (int e = 0; e < Ec; e++) gsh[warp][e] = gacc[e];
    __syncthreads();
    if (tid == 0) {
        float lg[Ec];
        #pragma unroll
        for (int e = 0; e < Ec; e++) {
            float v = 0.f;
            #pragma unroll
            for (int w = 0; w < 8; w++) v += gsh[w][e];
            lg[e] = v;
        }
        int e0 = 0; float l0 = lg[0];
        #pragma unroll
        for (int e = 1; e < Ec; e++) if (lg[e] > l0) { l0 = lg[e]; e0 = e; }
        int e1 = -1; float l1 = -3.4e38f;
        #pragma unroll
        for (int e = 0; e < Ec; e++) {
            if (e == e0) continue;
            if (lg[e] > l1) { l1 = lg[e]; e1 = e; }
        }
        float t1 = expf(l1 - l0);
        float w0 = 1.f / (1.f + t1);
        float w1 = t1 / (1.f + t1);
        wslot[2 * t]     = w0;
        wslot[2 * t + 1] = w1;
        int p0 = atomicAdd(&ecount[e0], 1);
        elist[e0 * NT + p0] = 2 * t;
        int p1 = atomicAdd(&ecount[e1], 1);
        elist[e1 * NT + p1] = 2 * t + 1;
    }
}

// ---------------------------------------------------------------------------
// tgemm v6 (hybrid): A = pre-split global planes (pure LDG->STS), B = fp32
// with in-kernel split (R13 loader). 128x128 tile, BK=16, double-buffered,
// ONE barrier/ktile. 8 warps 2(M) x 4(N), warp tile 64x32.
// EPI: 0 none, 1 +resid, 2 silu, 3 *wslot. GATHER via elist.
// Output fp32 (C) or planes (CH/CL non-null).
// Optional second op via blockIdx.z==1 (non-gather).
// ---------------------------------------------------------------------------
constexpr int PA = 12;
constexpr int PB = 136;

template <int EPI, bool GATHER>
__global__ __launch_bounds__(256, 2) void tgemm_kernel(
    const uint32_t* __restrict__ AH, const uint32_t* __restrict__ AL,
    const float* __restrict__ B, const float* __restrict__ resid,
    float* __restrict__ C, uint32_t* __restrict__ CH, uint32_t* __restrict__ CL,
    int K, int N,
    const int* __restrict__ elist, const int* __restrict__ ecount,
    const float* __restrict__ wslot, int ashift, size_t bExpertStride,
    const float* __restrict__ B2,
    float* __restrict__ C2, uint32_t* __restrict__ C2H, uint32_t* __restrict__ C2L,
    int N2)
{
    __shared__ uint32_t Ahi[2][128][PA], Alo[2][128][PA];
    __shared__ uint32_t Bhi[2][8][PB],   Blo[2][8][PB];

    const int tid  = threadIdx.x;
    const int warp = tid >> 5;
    const int lane = tid & 31;
    const int wy = warp & 1;
    const int wx = warp >> 1;
    const int mW = wy * 64;
    const int nW = wx * 32;
    const int g  = lane >> 2;
    const int lm = lane & 3;

    const int n0 = blockIdx.x * 128;
    const int KP = K >> 1;

    int e = 0, cnt = 0, rt = 0, m0 = 0;
    const float* Bb = B;
    float* Cf = C;
    uint32_t* CHp = CH;
    uint32_t* CLp = CL;
    int Nn = N;
    if (GATHER) {
        e = blockIdx.z;
        cnt = ecount[e];
        rt = blockIdx.y * 128;
        if (rt >= cnt) return;
        Bb = B + (size_t)e * bExpertStride;
    } else {
        m0 = blockIdx.y * 128;
        if (B2 != nullptr && blockIdx.z == 1) {
            Bb = B2; Cf = C2; CHp = C2H; CLp = C2L; Nn = N2;
            if (n0 >= Nn) return;
        }
    }

    const int arow = tid >> 1;
    const int akp0 = (tid & 1) * 4;
    const int bkp  = tid >> 5;
    const int bn   = (tid & 31) * 4;

    size_t aoff;
    bool avalid = true;
    if (GATHER) {
        int gr = rt + arow;
        avalid = gr < cnt;
        int slot = avalid ? elist[e * NT + gr] : 0;
        aoff = (size_t)(slot >> ashift) * KP + akp0;
    } else {
        aoff = (size_t)(m0 + arow) * KP + akp0;
    }
    const float* bptr = Bb + n0 + bn;

    float acc[4][4][4];
    #pragma unroll
    for (int i = 0; i < 4; i++)
        #pragma unroll
        for (int j = 0; j < 4; j++)
            #pragma unroll
            for (int c = 0; c < 4; c++) acc[i][j][c] = 0.f;

    const int KT = K >> 4;
    const uint4 uz = make_uint4(0, 0, 0, 0);

    // stage tile 0
    uint4 aH = avalid ? *(const uint4*)(AH + aoff) : uz;
    uint4 aL = avalid ? *(const uint4*)(AL + aoff) : uz;
    float4 b0v = *(const float4*)(bptr + (size_t)(2 * bkp) * Nn);
    float4 b1v = *(const float4*)(bptr + (size_t)(2 * bkp + 1) * Nn);

    for (int kt = 0; kt < KT; kt++) {
        const int cb = kt & 1;
        *(uint4*)&Ahi[cb][arow][akp0] = aH;
        *(uint4*)&Alo[cb][arow][akp0] = aL;
        {
            uint32_t h, l;
            uint4 vh, vl;
            split2(b0v.x, b1v.x, h, l); vh.x = h; vl.x = l;
            split2(b0v.y, b1v.y, h, l); vh.y = h; vl.y = l;
            split2(b0v.z, b1v.z, h, l); vh.z = h; vl.z = l;
            split2(b0v.w, b1v.w, h, l); vh.w = h; vl.w = l;
            *(uint4*)&Bhi[cb][bkp][bn] = vh;
            *(uint4*)&Blo[cb][bkp][bn] = vl;
        }
        __syncthreads();            // single barrier per iteration

        if (kt + 1 < KT) {
            size_t ka = aoff + (size_t)(kt + 1) * 8;
            aH = avalid ? *(const uint4*)(AH + ka) : uz;
            aL = avalid ? *(const uint4*)(AL + ka) : uz;
            int k0 = (kt + 1) * 16;
            b0v = *(const float4*)(bptr + (size_t)(k0 + 2 * bkp) * Nn);
            b1v = *(const float4*)(bptr + (size_t)(k0 + 2 * bkp + 1) * Nn);
        }

        uint32_t ahi[4][4], alo[4][4];
        #pragma unroll
        for (int mi = 0; mi < 4; mi++) {
            int r = mW + mi * 16 + g;
            ahi[mi][0] = Ahi[cb][r    ][lm];
            ahi[mi][1] = Ahi[cb][r + 8][lm];
            ahi[mi][2] = Ahi[cb][r    ][lm + 4];
            ahi[mi][3] = Ahi[cb][r + 8][lm + 4];
            alo[mi][0] = Alo[cb][r    ][lm];
            alo[mi][1] = Alo[cb][r + 8][lm];
            alo[mi][2] = Alo[cb][r    ][lm + 4];
            alo[mi][3] = Alo[cb][r + 8][lm + 4];
        }
        #pragma unroll
        for (int ni = 0; ni < 4; ni++) {
            int c = nW + ni * 8 + g;
            uint32_t bhi[2], blo[2];
            bhi[0] = Bhi[cb][lm    ][c];
            bhi[1] = Bhi[cb][lm + 4][c];
            blo[0] = Blo[cb][lm    ][c];
            blo[1] = Blo[cb][lm + 4][c];
            #pragma unroll
            for (int mi = 0; mi < 4; mi++) {
                mma_bf16(acc[mi][ni], ahi[mi], bhi);
                mma_bf16(acc[mi][ni], ahi[mi], blo);
                mma_bf16(acc[mi][ni], alo[mi], bhi);
            }
        }
    }

    #pragma unroll
    for (int mi = 0; mi < 4; mi++) {
        int r0 = mW + mi * 16 + g;
        int r1 = r0 + 8;
        size_t row0, row1;
        bool v0 = true, v1 = true;
        float w0 = 1.f, w1 = 1.f;
        if (GATHER) {
            int g0 = rt + r0, g1 = rt + r1;
            v0 = g0 < cnt; v1 = g1 < cnt;
            int s0 = v0 ? elist[e * NT + g0] : 0;
            int s1 = v1 ? elist[e * NT + g1] : 0;
            row0 = (size_t)s0;
            row1 = (size_t)s1;
            if (EPI == 3) { w0 = v0 ? wslot[s0] : 0.f; w1 = v1 ? wslot[s1] : 0.f; }
        } else {
            row0 = (size_t)(m0 + r0);
            row1 = (size_t)(m0 + r1);
        }
        #pragma unroll
        for (int ni = 0; ni < 4; ni++) {
            int col = n0 + nW + ni * 8 + 2 * lm;
            float x0 = acc[mi][ni][0], x1 = acc[mi][ni][1];
            float x2 = acc[mi][ni][2], x3 = acc[mi][ni][3];
            if (EPI == 1) {
                const float* rp0 = resid + row0 * Nn + col;
                const float* rp1 = resid + row1 * Nn + col;
                x0 += rp0[0]; x1 += rp0[1];
                x2 += rp1[0]; x3 += rp1[1];
            } else if (EPI == 2) {
                x0 = x0 / (1.f + __expf(-x0));
                x1 = x1 / (1.f + __expf(-x1));
                x2 = x2 / (1.f + __expf(-x2));
                x3 = x3 / (1.f + __expf(-x3));
            } else if (EPI == 3) {
                x0 *= w0; x1 *= w0; x2 *= w1; x3 *= w1;
            }
            if (CHp) {
                uint32_t h, l;
                if (v0) {
                    split2(x0, x1, h, l);
                    CHp[row0 * (Nn / 2) + (col >> 1)] = h;
                    CLp[row0 * (Nn / 2) + (col >> 1)] = l;
                }
                if (v1) {
                    split2(x2, x3, h, l);
                    CHp[row1 * (Nn / 2) + (col >> 1)] = h;
                    CLp[row1 * (Nn / 2) + (col >> 1)] = l;
                }
            } else {
                if (v0) *(float2*)&Cf[row0 * Nn + col] = make_float2(x0, x1);
                if (v1) *(float2*)&Cf[row1 * Nn + col] = make_float2(x2, x3);
            }
        }
    }
}

__global__ __launch_bounds__(256) void rope_kernel(
    float* __restrict__ q, float* __restrict__ k, const float* __restrict__ freqs)
{
    int p = blockIdx.x * 256 + threadIdx.x;
    int t = p >> 9;
    int r = p & 511;
    int hh = r >> 6;
    int i  = r & 63;
    int s  = t & (Sc - 1);
    float f = freqs[s * 64 + i];
    float c = cosf(f), sn = sinf(f);
    size_t base = (size_t)t * Dc + hh * HDc + 2 * i;
    float e = q[base], o = q[base + 1];
    q[base] = e * c - o * sn; q[base + 1] = e * sn + o * c;
    e = k[base]; o = k[base + 1];
    k[base] = e * c - o * sn; k[base + 1] = e * sn + o * c;
}

// ---------------------------------------------------------------------------
// Flash attention (round-14: plane output; passing)
// ---------------------------------------------------------------------------
constexpr int QKP = 68;
constexpr int VP  = 136;
constexpr int PP  = 36;
constexpr int FQH = 0;
constexpr int FQL = FQH + 64 * QKP;
constexpr int FKH = FQL + 64 * QKP;
constexpr int FKL = FKH + 64 * QKP;
constexpr int FVH = FKL + 64 * QKP;
constexpr int FVL = FVH + 32 * VP;
constexpr int FPH = FVL + 32 * VP;
constexpr int FPL = FPH + 64 * PP;
constexpr int FRM = FPL + 64 * PP;
constexpr int FRS = FRM + 128;
constexpr int FLASH_SMEM = (FRS + 128) * 4;

__global__ __launch_bounds__(256) void flash_tc_kernel(
    const float* __restrict__ q, const float* __restrict__ k,
    const float* __restrict__ v, uint32_t* __restrict__ aoH,
    uint32_t* __restrict__ aoL)
{
    extern __shared__ uint32_t smu[];
    uint32_t* QH = smu + FQH;
    uint32_t* QL = smu + FQL;
    uint32_t* KH = smu + FKH;
    uint32_t* KL = smu + FKL;
    uint32_t* VH = smu + FVH;
    uint32_t* VL = smu + FVL;
    uint32_t* PH = smu + FPH;
    uint32_t* PL = smu + FPL;
    float* RM = (float*)(smu + FRM);
    float* RS = (float*)(smu + FRS);

    const int tid  = threadIdx.x;
    const int warp = tid >> 5;
    const int lane = tid & 31;
    const int wy = warp >> 1;
    const int wx = warp & 1;
    const int g  = lane >> 2;
    const int lm = lane & 3;

    const int qb = (gridDim.x - 1) - blockIdx.x;
    const int hh = blockIdx.y, b = blockIdx.z;
    const size_t qbase = ((size_t)(b * Sc + qb * 64)) * Dc + hh * HDc;
    const float scale = 0.08838834764831845f;

    const int row0 = wy * 16 + g;
    const int row1 = row0 + 8;

    #pragma unroll
    for (int i = 0; i < 8; i++) {
        int li = tid + i * 256;
        int r = li >> 5, c = (li & 31) * 4;
        float4 val = *(const float4*)(q + qbase + (size_t)r * Dc + c);
        uint32_t h, l;
        split2(val.x * scale, val.y * scale, h, l);
        QH[r * QKP + c / 2] = h; QL[r * QKP + c / 2] = l;
        split2(val.z * scale, val.w * scale, h, l);
        QH[r * QKP + c / 2 + 1] = h; QL[r * QKP + c / 2 + 1] = l;
    }

    float oacc[8][4];
    #pragma unroll
    for (int ni = 0; ni < 8; ni++)
        #pragma unroll
        for (int c = 0; c < 4; c++) oacc[ni][c] = 0.f;
    float m0s = -1e30f, m1s = -1e30f, l0s = 0.f, l1s = 0.f;

    for (int kb = 0; kb <= qb; kb++) {
        const size_t kbase = ((size_t)(b * Sc + kb * 64)) * Dc + hh * HDc;
        #pragma unroll
        for (int i = 0; i < 8; i++) {
            int li = tid + i * 256;
            int r = li >> 5, c = (li & 31) * 4;
            float4 kv = *(const float4*)(k + kbase + (size_t)r * Dc + c);
            uint32_t h, l;
            split2(kv.x, kv.y, h, l);
            KH[r * QKP + c / 2] = h; KL[r * QKP + c / 2] = l;
            split2(kv.z, kv.w, h, l);
            KH[r * QKP + c / 2 + 1] = h; KL[r * QKP + c / 2 + 1] = l;
        }
        #pragma unroll
        for (int i = 0; i < 4; i++) {
            int li = tid + i * 256;
            int j = li >> 5, c = (li & 31) * 4;
            float4 v0 = *(const float4*)(v + kbase + (size_t)(2 * j) * Dc + c);
            float4 v1 = *(const float4*)(v + kbase + (size_t)(2 * j + 1) * Dc + c);
            uint32_t h, l;
            uint4 vh, vl;
            split2(v0.x, v1.x, h, l); vh.x = h; vl.x = l;
            split2(v0.y, v1.y, h, l); vh.y = h; vl.y = l;
            split2(v0.z, v1.z, h, l); vh.z = h; vl.z = l;
            split2(v0.w, v1.w, h, l); vh.w = h; vl.w = l;
            *(uint4*)&VH[j * VP + c] = vh;
            *(uint4*)&VL[j * VP + c] = vl;
        }
        __syncthreads();

        float sacc[4][4];
        #pragma unroll
        for (int ni = 0; ni < 4; ni++)
            #pragma unroll
            for (int c = 0; c < 4; c++) sacc[ni][c] = 0.f;

        #pragma unroll
        for (int ks = 0; ks < 8; ks++) {
            int kpb = ks * 8;
            uint32_t ahi[4], alo[4];
            ahi[0] = QH[row0 * QKP + kpb + lm];
            ahi[1] = QH[row1 * QKP + kpb + lm];
            ahi[2] = QH[row0 * QKP + kpb + lm + 4];
            ahi[3] = QH[row1 * QKP + kpb + lm + 4];
            alo[0] = QL[row0 * QKP + kpb + lm];
            alo[1] = QL[row1 * QKP + kpb + lm];
            alo[2] = QL[row0 * QKP + kpb + lm + 4];
            alo[3] = QL[row1 * QKP + kpb + lm + 4];
            #pragma unroll
            for (int ni = 0; ni < 4; ni++) {
                int ck = wx * 32 + ni * 8 + g;
                uint32_t bhi[2], blo[2];
                bhi[0] = KH[ck * QKP + kpb + lm];
                bhi[1] = KH[ck * QKP + kpb + lm + 4];
                blo[0] = KL[ck * QKP + kpb + lm];
                blo[1] = KL[ck * QKP + kpb + lm + 4];
                mma_bf16(sacc[ni], ahi, bhi);
                mma_bf16(sacc[ni], ahi, blo);
                mma_bf16(sacc[ni], alo, bhi);
            }
        }

        if (kb == qb) {
            int qa0 = qb * 64 + row0;
            int qa1 = qb * 64 + row1;
            #pragma unroll
            for (int ni = 0; ni < 4; ni++) {
                int ka = kb * 64 + wx * 32 + ni * 8 + 2 * lm;
                if (ka     > qa0) sacc[ni][0] = -1e30f;
                if (ka + 1 > qa0) sacc[ni][1] = -1e30f;
                if (ka     > qa1) sacc[ni][2] = -1e30f;
                if (ka + 1 > qa1) sacc[ni][3] = -1e30f;
            }
        }

        float rm0 = -1e30f, rm1 = -1e30f;
        #pragma unroll
        for (int ni = 0; ni < 4; ni++) {
            rm0 = fmaxf(rm0, fmaxf(sacc[ni][0], sacc[ni][1]));
            rm1 = fmaxf(rm1, fmaxf(sacc[ni][2], sacc[ni][3]));
        }
        rm0 = fmaxf(rm0, __shfl_xor_sync(0xffffffffu, rm0, 1));
        rm0 = fmaxf(rm0, __shfl_xor_sync(0xffffffffu, rm0, 2));
        rm1 = fmaxf(rm1, __shfl_xor_sync(0xffffffffu, rm1, 1));
        rm1 = fmaxf(rm1, __shfl_xor_sync(0xffffffffu, rm1, 2));
        if (lm == 0) {
            RM[row0 * 2 + wx] = rm0;
            RM[row1 * 2 + wx] = rm1;
        }
        __syncthreads();

        float mn0 = fmaxf(m0s, fmaxf(RM[row0 * 2], RM[row0 * 2 + 1]));
        float mn1 = fmaxf(m1s, fmaxf(RM[row1 * 2], RM[row1 * 2 + 1]));

        float ps0 = 0.f, ps1 = 0.f;
        #pragma unroll
        for (int ni = 0; ni < 4; ni++) {
            float p0 = __expf(sacc[ni][0] - mn0);
            float p1 = __expf(sacc[ni][1] - mn0);
            float p2 = __expf(sacc[ni][2] - mn1);
            float p3 = __expf(sacc[ni][3] - mn1);
            ps0 += p0 + p1; ps1 += p2 + p3;
            int kpw = wx * 16 + ni * 4 + lm;
            uint32_t h, l;
            split2(p0, p1, h, l);
            PH[row0 * PP + kpw] = h; PL[row0 * PP + kpw] = l;
            split2(p2, p3, h, l);
            PH[row1 * PP + kpw] = h; PL[row1 * PP + kpw] = l;
        }
        ps0 += __shfl_xor_sync(0xffffffffu, ps0, 1);
        ps0 += __shfl_xor_sync(0xffffffffu, ps0, 2);
        ps1 += __shfl_xor_sync(0xffffffffu, ps1, 1);
        ps1 += __shfl_xor_sync(0xffffffffu, ps1, 2);
        if (lm == 0) {
            RS[row0 * 2 + wx] = ps0;
            RS[row1 * 2 + wx] = ps1;
        }
        __syncthreads();

        float sc0 = __expf(m0s - mn0);
        float sc1 = __expf(m1s - mn1);
        l0s = l0s * sc0 + RS[row0 * 2] + RS[row0 * 2 + 1];
        l1s = l1s * sc1 + RS[row1 * 2] + RS[row1 * 2 + 1];
        m0s = mn0; m1s = mn1;
        #pragma unroll
        for (int ni = 0; ni < 8; ni++) {
            oacc[ni][0] *= sc0; oacc[ni][1] *= sc0;
            oacc[ni][2] *= sc1; oacc[ni][3] *= sc1;
        }

        #pragma unroll
        for (int ks = 0; ks < 4; ks++) {
            int kpb = ks * 8;
            uint32_t ahi[4], alo[4];
            ahi[0] = PH[row0 * PP + kpb + lm];
            ahi[1] = PH[row1 * PP + kpb + lm];
            ahi[2] = PH[row0 * PP + kpb + lm + 4];
            ahi[3] = PH[row1 * PP + kpb + lm + 4];
            alo[0] = PL[row0 * PP + kpb + lm];
            alo[1] = PL[row1 * PP + kpb + lm];
            alo[2] = PL[row0 * PP + kpb + lm + 4];
            alo[3] = PL[row1 * PP + kpb + lm + 4];
            #pragma unroll
            for (int ni = 0; ni < 8; ni++) {
                int vc = wx * 64 + ni * 8 + g;
                uint32_t bhi[2], blo[2];
                bhi[0] = VH[(kpb + lm)     * VP + vc];
                bhi[1] = VH[(kpb + lm + 4) * VP + vc];
                blo[0] = VL[(kpb + lm)     * VP + vc];
                blo[1] = VL[(kpb + lm + 4) * VP + vc];
                mma_bf16(oacc[ni], ahi, bhi);
                mma_bf16(oacc[ni], ahi, blo);
                mma_bf16(oacc[ni], alo, bhi);
            }
        }
        __syncthreads();
    }

    float inv0 = 1.f / l0s;
    float inv1 = 1.f / l1s;
    const size_t pbase = qbase >> 1;
    #pragma unroll
    for (int ni = 0; ni < 8; ni++) {
        int col = wx * 64 + ni * 8 + 2 * lm;
        uint32_t h, l;
        split2(oacc[ni][0] * inv0, oacc[ni][1] * inv0, h, l);
        aoH[pbase + (size_t)row0 * (Dc / 2) + (col >> 1)] = h;
        aoL[pbase + (size_t)row0 * (Dc / 2) + (col >> 1)] = l;
        split2(oacc[ni][2] * inv1, oacc[ni][3] * inv1, h, l);
        aoH[pbase + (size_t)row1 * (Dc / 2) + (col >> 1)] = h;
        aoL[pbase + (size_t)row1 * (Dc / 2) + (col >> 1)] = l;
    }
}

__global__ __launch_bounds__(256) void combine_kernel(
    const float* __restrict__ h, const float* __restrict__ moeout,
    float* __restrict__ out)
{
    size_t i = (size_t)blockIdx.x * 256 + threadIdx.x;
    size_t t = i >> 10, d = i & 1023;
    out[i] = h[i] + moeout[(2 * t) * (size_t)Dc + d]
                  + moeout[(2 * t + 1) * (size_t)Dc + d];
}

extern "C" void kernel_launch(void* const* d_in, const int* in_sizes, int n_in,
                              void* d_out, int out_size)
{
    const float* x     = (const float*)d_in[0];
    const float* freqs = (const float*)d_in[1];
    const float* g1    = (const float*)d_in[2];
    const float* b1    = (const float*)d_in[3];
    const float* g2    = (const float*)d_in[4];
    const float* b2    = (const float*)d_in[5];
    const float* Wq    = (const float*)d_in[6];
    const float* Wdkv  = (const float*)d_in[7];
    const float* Wuk   = (const float*)d_in[8];
    const float* Wuv   = (const float*)d_in[9];
    const float* Wo    = (const float*)d_in[10];
    const float* Wg    = (const float*)d_in[11];
    const float* W1    = (const float*)d_in[12];
    const float* W2    = (const float*)d_in[13];
    float* out = (float*)d_out;

    void* bufp = nullptr;
    cudaGetSymbolAddress(&bufp, g_buf);
    float* buf   = (float*)bufp;
    float* qb_   = buf + OFF_Q;
    float* kb_   = buf + OFF_K;
    float* vb_   = buf + OFF_V;
    float* h     = buf + OFF_H;
    float* moeo  = buf + OFF_MOE;
    float* wslot = buf + OFF_WSLOT;
    int*   elist = (int*)(buf + OFF_ELIST);
    int*   ecnt  = (int*)(buf + OFF_ECNT);
    uint32_t* ub = (uint32_t*)bufp;
    uint32_t* xnH  = ub + OFF_XNH;
    uint32_t* xnL  = ub + OFF_XNL;
    uint32_t* latH = ub + OFF_LATH;
    uint32_t* latL = ub + OFF_LATL;
    uint32_t* aoH  = ub + OFF_AOH;
    uint32_t* aoL  = ub + OFF_AOL;
    uint32_t* hnH  = ub + OFF_HNH;
    uint32_t* hnL  = ub + OFF_HNL;
    uint32_t* actH = ub + OFF_ACTH;
    uint32_t* actL = ub + OFF_ACTL;

    cudaFuncSetAttribute(flash_tc_kernel,
                         cudaFuncAttributeMaxDynamicSharedMemorySize, FLASH_SMEM);

    reset_kernel<<<1, 32>>>(ecnt);
    ln_kernel<false><<<NT, 256>>>(x, g1, b1, xnH, xnL,
                                  nullptr, nullptr, nullptr, nullptr);

    // fused Wq (z=0 -> q fp32) + Wdkv (z=1 -> lat planes)
    tgemm_kernel<0, false><<<dim3(Dc / 128, NT / 128, 2), 256>>>(
        xnH, xnL, Wq, nullptr, qb_, nullptr, nullptr, Dc, Dc,
        nullptr, nullptr, nullptr, 0, 0,
        Wdkv, nullptr, latH, latL, Lc);
    // fused Wuk (z=0 -> k fp32) + Wuv (z=1 -> v fp32)
    tgemm_kernel<0, false><<<dim3(Dc / 128, NT / 128, 2), 256>>>(
        latH, latL, Wuk, nullptr, kb_, nullptr, nullptr, Lc, Dc,
        nullptr, nullptr, nullptr, 0, 0,
        Wuv, vb_, nullptr, nullptr, Dc);

    rope_kernel<<<(NT * (Dc / 2)) / 256, 256>>>(qb_, kb_, freqs);

    flash_tc_kernel<<<dim3(Sc / 64, Hc, Bc), 256, FLASH_SMEM>>>(
        qb_, kb_, vb_, aoH, aoL);

    // Wo: A = ao planes, +resid x -> h fp32
    tgemm_kernel<1, false><<<dim3(Dc / 128, NT / 128), 256>>>(
        aoH, aoL, Wo, x, h, nullptr, nullptr, Dc, Dc,
        nullptr, nullptr, nullptr, 0, 0,
        nullptr, nullptr, nullptr, nullptr, 0);

    // second LN + fused gate -> hn planes
    ln_kernel<true><<<NT, 256>>>(h, g2, b2, hnH, hnL, Wg, wslot, elist, ecnt);

    // MoE gemm1: A = hn planes (slot>>1), silu -> act planes
    tgemm_kernel<2, true><<<dim3(Fc / 128, NT / 128, Ec), 256>>>(
        hnH, hnL, W1, nullptr, nullptr, actH, actL, Dc, Fc,
        elist, ecnt, nullptr, 1, (size_t)Dc * Fc,
        nullptr, nullptr, nullptr, nullptr, 0);
    // MoE gemm2: A = act planes (slot), *wslot -> moeo fp32
    tgemm_kernel<3, true><<<dim3(Dc / 128, NT / 128, Ec), 256>>>(
        actH, actL, W2, nullptr, moeo, nullptr, nullptr, Fc, Dc,
        elist, ecnt, wslot, 0, (size_t)Fc * Dc,
        nullptr, nullptr, nullptr, nullptr, 0);

    combine_kernel<<<(NT * Dc) / 256, 256>>>(h, moeo, out);
}

// round 16
// speedup vs baseline: 1.2756x; 1.1428x over previous
#include <cuda_runtime.h>
#include <cuda_bf16.h>
#include <math.h>
#include <stdint.h>

constexpr int Bc  = 2;
constexpr int Sc  = 2048;
constexpr int Dc  = 1024;
constexpr int Lc  = 512;
constexpr int Hc  = 8;
constexpr int HDc = 128;
constexpr int Ec  = 8;
constexpr int Fc  = 4096;
constexpr int NT  = Bc * Sc;

constexpr size_t OFF_XN    = 0;
constexpr size_t OFF_Q     = OFF_XN    + (size_t)NT * Dc;
constexpr size_t OFF_K     = OFF_Q     + (size_t)NT * Dc;
constexpr size_t OFF_V     = OFF_K     + (size_t)NT * Dc;
constexpr size_t OFF_LAT   = OFF_V     + (size_t)NT * Dc;
constexpr size_t OFF_AO    = OFF_LAT   + (size_t)NT * Lc;
constexpr size_t OFF_H     = OFF_AO    + (size_t)NT * Dc;
constexpr size_t OFF_HN    = OFF_H     + (size_t)NT * Dc;
constexpr size_t OFF_ACT   = OFF_HN    + (size_t)NT * Dc;
constexpr size_t OFF_MOE   = OFF_ACT   + (size_t)2 * NT * Fc;
constexpr size_t OFF_WSLOT = OFF_MOE   + (size_t)2 * NT * Dc;
constexpr size_t OFF_ELIST = OFF_WSLOT + (size_t)2 * NT;
constexpr size_t OFF_ECNT  = OFF_ELIST + (size_t)Ec * NT;
constexpr size_t BUF_TOTAL = OFF_ECNT + 64;

__device__ float g_buf[BUF_TOTAL];

__global__ void reset_kernel(int* ecount) {
    if (threadIdx.x < Ec) ecount[threadIdx.x] = 0;
}

// LayerNorm; optionally fused MoE gate (round-13, passing)
template <bool GATE>
__global__ __launch_bounds__(256) void ln_kernel(
    const float* __restrict__ x, const float* __restrict__ g,
    const float* __restrict__ b, float* __restrict__ y,
    const float* __restrict__ Wg, float* __restrict__ wslot,
    int* __restrict__ elist, int* __restrict__ ecount)
{
    int t = blockIdx.x;
    int tid = threadIdx.x;
    const float* xr = x + (size_t)t * Dc;
    float s = 0.f, s2 = 0.f;
    #pragma unroll
    for (int i = tid; i < Dc; i += 256) { float v = xr[i]; s += v; s2 += v * v; }
    __shared__ float sh[2][256];
    __shared__ float gsh[8][Ec];
    sh[0][tid] = s; sh[1][tid] = s2;
    __syncthreads();
    for (int st = 128; st > 0; st >>= 1) {
        if (tid < st) { sh[0][tid] += sh[0][tid + st]; sh[1][tid] += sh[1][tid + st]; }
        __syncthreads();
    }
    float mu   = sh[0][0] * (1.f / Dc);
    float var  = sh[1][0] * (1.f / Dc) - mu * mu;
    float rstd = rsqrtf(var + 1e-5f);
    float* yr = y + (size_t)t * Dc;

    if (!GATE) {
        #pragma unroll
        for (int i = tid; i < Dc; i += 256)
            yr[i] = (xr[i] - mu) * rstd * g[i] + b[i];
        return;
    }

    float gacc[Ec];
    #pragma unroll
    for (int e = 0; e < Ec; e++) gacc[e] = 0.f;
    #pragma unroll
    for (int i = tid; i < Dc; i += 256) {
        float yv = (xr[i] - mu) * rstd * g[i] + b[i];
        yr[i] = yv;
        const float* wr = Wg + (size_t)i * Ec;
        #pragma unroll
        for (int e = 0; e < Ec; e++) gacc[e] = fmaf(yv, wr[e], gacc[e]);
    }
    #pragma unroll
    for (int e = 0; e < Ec; e++)
        #pragma unroll
        for (int m = 16; m >= 1; m >>= 1)
            gacc[e] += __shfl_xor_sync(0xffffffffu, gacc[e], m);
    int warp = tid >> 5, lane = tid & 31;
    if (lane == 0)
        #pragma unroll
        for (int e = 0; e < Ec; e++) gsh[warp][e] = gacc[e];
    __syncthreads();
    if (tid == 0) {
        float lg[Ec];
        #pragma unroll
        for (int e = 0; e < Ec; e++) {
            float v = 0.f;
            #pragma unroll
            for (int w = 0; w < 8; w++) v += gsh[w][e];
            lg[e] = v;
        }
        int e0 = 0; float l0 = lg[0];
        #pragma unroll
        for (int e = 1; e < Ec; e++) if (lg[e] > l0) { l0 = lg[e]; e0 = e; }
        int e1 = -1; float l1 = -3.4e38f;
        #pragma unroll
        for (int e = 0; e < Ec; e++) {
            if (e == e0) continue;
            if (lg[e] > l1) { l1 = lg[e]; e1 = e; }
        }
        float t1 = expf(l1 - l0);
        float w0 = 1.f / (1.f + t1);
        float w1 = t1 / (1.f + t1);
        wslot[2 * t]     = w0;
        wslot[2 * t + 1] = w1;
        int p0 = atomicAdd(&ecount[e0], 1);
        elist[e0 * NT + p0] = 2 * t;
        int p1 = atomicAdd(&ecount[e1], 1);
        elist[e1 * NT + p1] = 2 * t + 1;
    }
}

// split a pair of fp32 into bf16x2 hi + bf16x2 lo  (first arg in low half)
__device__ __forceinline__ void split2(float x0, float x1, uint32_t& hi, uint32_t& lo) {
    uint32_t h;
    asm("cvt.rn.bf16x2.f32 %0, %1, %2;" : "=r"(h) : "f"(x1), "f"(x0));
    float h0 = __uint_as_float(h << 16);
    float h1 = __uint_as_float(h & 0xffff0000u);
    uint32_t l;
    asm("cvt.rn.bf16x2.f32 %0, %1, %2;" : "=r"(l) : "f"(x1 - h1), "f"(x0 - h0));
    hi = h; lo = l;
}

__device__ __forceinline__ void mma_bf16(float* d, const uint32_t* a, const uint32_t* b) {
    asm volatile(
        "mma.sync.aligned.m16n8k16.row.col.f32.bf16.bf16.f32 "
        "{%0,%1,%2,%3}, {%4,%5,%6,%7}, {%8,%9}, {%0,%1,%2,%3};"
        : "+f"(d[0]), "+f"(d[1]), "+f"(d[2]), "+f"(d[3])
        : "r"(a[0]), "r"(a[1]), "r"(a[2]), "r"(a[3]), "r"(b[0]), "r"(b[1]));
}

__device__ __forceinline__ void ldsm_x4(uint32_t* r, uint32_t addr) {
    asm volatile(
        "ldmatrix.sync.aligned.m8n8.x4.shared.b16 {%0,%1,%2,%3}, [%4];"
        : "=r"(r[0]), "=r"(r[1]), "=r"(r[2]), "=r"(r[3]) : "r"(addr));
}
__device__ __forceinline__ void ldsm_x4t(uint32_t* r, uint32_t addr) {
    asm volatile(
        "ldmatrix.sync.aligned.m8n8.x4.trans.shared.b16 {%0,%1,%2,%3}, [%4];"
        : "=r"(r[0]), "=r"(r[1]), "=r"(r[2]), "=r"(r[3]) : "r"(addr));
}

// ---------------------------------------------------------------------------
// tgemm v7: R13 structure + ldmatrix fragment loads.
// A smem: paired-k u32 [128][PA]; B smem: bf16 [k16][n128] as u32 [16][PBN].
// 128x128 tile, BK=16, double-buffered, ONE barrier/ktile, 8 warps 2(M)x4(N).
// EPI: 0 none, 1 +resid, 2 silu, 3 *wslot. GATHER via elist.
// Optional second op (B2,C2,N2) via blockIdx.z==1 (non-gather).
// ---------------------------------------------------------------------------
constexpr int PA  = 12;
constexpr int PBN = 68;

template <int EPI, bool GATHER>
__global__ __launch_bounds__(256, 2) void tgemm_kernel(
    const float* __restrict__ A, const float* __restrict__ B,
    const float* __restrict__ resid, float* __restrict__ C,
    int M, int K, int N,
    const int* __restrict__ elist, const int* __restrict__ ecount,
    const float* __restrict__ wslot, int ashift, size_t bExpertStride,
    const float* __restrict__ B2, float* __restrict__ C2, int N2)
{
    __shared__ uint32_t Ahi[2][128][PA], Alo[2][128][PA];
    __shared__ uint32_t Bhi[2][16][PBN], Blo[2][16][PBN];

    const int tid  = threadIdx.x;
    const int warp = tid >> 5;
    const int lane = tid & 31;
    const int wy = warp & 1;
    const int wx = warp >> 1;
    const int mW = wy * 64;
    const int nW = wx * 32;
    const int g  = lane >> 2;
    const int lm = lane & 3;

    const int n0 = blockIdx.x * 128;

    int e = 0, cnt = 0, rt = 0, m0 = 0;
    const float* Bb = B;
    float* Cw = C;
    int Nn = N;
    if (GATHER) {
        e = blockIdx.z;
        cnt = ecount[e];
        rt = blockIdx.y * 128;
        if (rt >= cnt) return;
        Bb = B + (size_t)e * bExpertStride;
    } else {
        m0 = blockIdx.y * 128;
        if (B2 != nullptr && blockIdx.z == 1) {
            Bb = B2; Cw = C2; Nn = N2;
            if (n0 >= Nn) return;
        }
    }

    // A loader (R13): 2 threads per row, 8 floats each along k
    const int arow  = tid >> 1;
    const int acolg = (tid & 1) * 8;
    const int akp0  = (tid & 1) * 4;
    // B loader: 16 threads per k-row, 8 floats each along n
    const int brow  = tid >> 4;          // 0..15
    const int bn8   = (tid & 15) * 8;    // float col
    const int bn4   = (tid & 15) * 4;    // u32 col

    const float* aptr;
    bool avalid = true;
    if (GATHER) {
        int gr = rt + arow;
        avalid = gr < cnt;
        int slot = avalid ? elist[e * NT + gr] : 0;
        aptr = A + (size_t)(slot >> ashift) * K + acolg;
    } else {
        aptr = A + (size_t)(m0 + arow) * K + acolg;
    }
    const float* bptr = Bb + n0 + bn8;

    // ldmatrix per-thread addresses
    const int aRow = (lane & 7) + ((lane & 8) ? 8 : 0);
    const int aKp  = (lane & 16) ? 4 : 0;
    const int bKr  = (lane & 7) + ((lane & 8) ? 8 : 0);
    const int bC4  = (nW >> 1) + ((lane & 16) ? 4 : 0);
    uint32_t aHad = (uint32_t)__cvta_generic_to_shared(&Ahi[0][mW + aRow][aKp]);
    uint32_t aLad = (uint32_t)__cvta_generic_to_shared(&Alo[0][mW + aRow][aKp]);
    uint32_t bHad = (uint32_t)__cvta_generic_to_shared(&Bhi[0][bKr][bC4]);
    uint32_t bLad = (uint32_t)__cvta_generic_to_shared(&Blo[0][bKr][bC4]);
    const uint32_t bufA = 128u * PA * 4u;
    const uint32_t bufB = 16u * PBN * 4u;
    const uint32_t miStride = 16u * PA * 4u;
    const uint32_t piStride = 8u * 4u;      // 8 u32 = 16 bf16 cols

    float acc[4][4][4];
    #pragma unroll
    for (int i = 0; i < 4; i++)
        #pragma unroll
        for (int j = 0; j < 4; j++)
            #pragma unroll
            for (int c = 0; c < 4; c++) acc[i][j][c] = 0.f;

    const int KT = K >> 4;
    const float4 fz = make_float4(0.f, 0.f, 0.f, 0.f);

    // stage tile 0
    float4 a0 = avalid ? *(const float4*)(aptr)     : fz;
    float4 a1 = avalid ? *(const float4*)(aptr + 4) : fz;
    float4 b0v = *(const float4*)(bptr + (size_t)brow * Nn);
    float4 b1v = *(const float4*)(bptr + (size_t)brow * Nn + 4);

    for (int kt = 0; kt < KT; kt++) {
        const int cb = kt & 1;
        {
            uint32_t h, l;
            uint4 vh, vl;
            // A: pairs along k (unchanged values)
            split2(a0.x, a0.y, h, l); vh.x = h; vl.x = l;
            split2(a0.z, a0.w, h, l); vh.y = h; vl.y = l;
            split2(a1.x, a1.y, h, l); vh.z = h; vl.z = l;
            split2(a1.z, a1.w, h, l); vh.w = h; vl.w = l;
            *(uint4*)&Ahi[cb][arow][akp0] = vh;
            *(uint4*)&Alo[cb][arow][akp0] = vl;
            // B: pairs along n -> bf16 [k][n] layout
            split2(b0v.x, b0v.y, h, l); vh.x = h; vl.x = l;
            split2(b0v.z, b0v.w, h, l); vh.y = h; vl.y = l;
            split2(b1v.x, b1v.y, h, l); vh.z = h; vl.z = l;
            split2(b1v.z, b1v.w, h, l); vh.w = h; vl.w = l;
            *(uint4*)&Bhi[cb][brow][bn4] = vh;
            *(uint4*)&Blo[cb][brow][bn4] = vl;
        }
        __syncthreads();            // single barrier per iteration

        if (kt + 1 < KT) {
            int k0 = (kt + 1) * 16;
            a0 = avalid ? *(const float4*)(aptr + k0)     : fz;
            a1 = avalid ? *(const float4*)(aptr + k0 + 4) : fz;
            b0v = *(const float4*)(bptr + (size_t)(k0 + brow) * Nn);
            b1v = *(const float4*)(bptr + (size_t)(k0 + brow) * Nn + 4);
        }

        // fragments via ldmatrix
        uint32_t ahi[4][4], alo[4][4];
        #pragma unroll
        for (int mi = 0; mi < 4; mi++) {
            ldsm_x4(ahi[mi], aHad + cb * bufA + mi * miStride);
            ldsm_x4(alo[mi], aLad + cb * bufA + mi * miStride);
        }
        #pragma unroll
        for (int pi = 0; pi < 2; pi++) {
            uint32_t bh[4], bl[4];
            ldsm_x4t(bh, bHad + cb * bufB + pi * piStride);
            ldsm_x4t(bl, bLad + cb * bufB + pi * piStride);
            #pragma unroll
            for (int q = 0; q < 2; q++) {
                const int ni = pi * 2 + q;
                uint32_t bhi[2] = { bh[2 * q], bh[2 * q + 1] };
                uint32_t blo[2] = { bl[2 * q], bl[2 * q + 1] };
                #pragma unroll
                for (int mi = 0; mi < 4; mi++) {
                    mma_bf16(acc[mi][ni], ahi[mi], bhi);
                    mma_bf16(acc[mi][ni], ahi[mi], blo);
                    mma_bf16(acc[mi][ni], alo[mi], bhi);
                }
            }
        }
    }

    #pragma unroll
    for (int mi = 0; mi < 4; mi++) {
        int r0 = mW + mi * 16 + g;
        int r1 = r0 + 8;
        size_t crow0, crow1;
        bool v0 = true, v1 = true;
        float w0 = 1.f, w1 = 1.f;
        if (GATHER) {
            int g0 = rt + r0, g1 = rt + r1;
            v0 = g0 < cnt; v1 = g1 < cnt;
            int s0 = v0 ? elist[e * NT + g0] : 0;
            int s1 = v1 ? elist[e * NT + g1] : 0;
            crow0 = (size_t)s0 * Nn;
            crow1 = (size_t)s1 * Nn;
            if (EPI == 3) { w0 = v0 ? wslot[s0] : 0.f; w1 = v1 ? wslot[s1] : 0.f; }
        } else {
            crow0 = (size_t)(m0 + r0) * Nn;
            crow1 = (size_t)(m0 + r1) * Nn;
        }
        #pragma unroll
        for (int ni = 0; ni < 4; ni++) {
            int col = n0 + nW + ni * 8 + 2 * lm;
            float x0 = acc[mi][ni][0], x1 = acc[mi][ni][1];
            float x2 = acc[mi][ni][2], x3 = acc[mi][ni][3];
            if (EPI == 1) {
                const float* rp0 = resid + crow0 + col;
                const float* rp1 = resid + crow1 + col;
                x0 += rp0[0]; x1 += rp0[1];
                x2 += rp1[0]; x3 += rp1[1];
            } else if (EPI == 2) {
                x0 = x0 / (1.f + __expf(-x0));
                x1 = x1 / (1.f + __expf(-x1));
                x2 = x2 / (1.f + __expf(-x2));
                x3 = x3 / (1.f + __expf(-x3));
            } else if (EPI == 3) {
                x0 *= w0; x1 *= w0; x2 *= w1; x3 *= w1;
            }
            if (v0) *(float2*)&Cw[crow0 + col] = make_float2(x0, x1);
            if (v1) *(float2*)&Cw[crow1 + col] = make_float2(x2, x3);
        }
    }
}

__global__ __launch_bounds__(256) void rope_kernel(
    float* __restrict__ q, float* __restrict__ k, const float* __restrict__ freqs)
{
    int p = blockIdx.x * 256 + threadIdx.x;
    int t = p >> 9;
    int r = p & 511;
    int hh = r >> 6;
    int i  = r & 63;
    int s  = t & (Sc - 1);
    float f = freqs[s * 64 + i];
    float c = cosf(f), sn = sinf(f);
    size_t base = (size_t)t * Dc + hh * HDc + 2 * i;
    float e = q[base], o = q[base + 1];
    q[base] = e * c - o * sn; q[base + 1] = e * sn + o * c;
    e = k[base]; o = k[base + 1];
    k[base] = e * c - o * sn; k[base + 1] = e * sn + o * c;
}

// ---------------------------------------------------------------------------
// Flash attention (round-13, unchanged)
// ---------------------------------------------------------------------------
constexpr int QKP = 68;
constexpr int VP  = 136;
constexpr int PP  = 36;
constexpr int FQH = 0;
constexpr int FQL = FQH + 64 * QKP;
constexpr int FKH = FQL + 64 * QKP;
constexpr int FKL = FKH + 64 * QKP;
constexpr int FVH = FKL + 64 * QKP;
constexpr int FVL = FVH + 32 * VP;
constexpr int FPH = FVL + 32 * VP;
constexpr int FPL = FPH + 64 * PP;
constexpr int FRM = FPL + 64 * PP;
constexpr int FRS = FRM + 128;
constexpr int FLASH_SMEM = (FRS + 128) * 4;

__global__ __launch_bounds__(256) void flash_tc_kernel(
    const float* __restrict__ q, const float* __restrict__ k,
    const float* __restrict__ v, float* __restrict__ ao)
{
    extern __shared__ uint32_t smu[];
    uint32_t* QH = smu + FQH;
    uint32_t* QL = smu + FQL;
    uint32_t* KH = smu + FKH;
    uint32_t* KL = smu + FKL;
    uint32_t* VH = smu + FVH;
    uint32_t* VL = smu + FVL;
    uint32_t* PH = smu + FPH;
    uint32_t* PL = smu + FPL;
    float* RM = (float*)(smu + FRM);
    float* RS = (float*)(smu + FRS);

    const int tid  = threadIdx.x;
    const int warp = tid >> 5;
    const int lane = tid & 31;
    const int wy = warp >> 1;
    const int wx = warp & 1;
    const int g  = lane >> 2;
    const int lm = lane & 3;

    const int qb = (gridDim.x - 1) - blockIdx.x;
    const int hh = blockIdx.y, b = blockIdx.z;
    const size_t qbase = ((size_t)(b * Sc + qb * 64)) * Dc + hh * HDc;
    const float scale = 0.08838834764831845f;

    const int row0 = wy * 16 + g;
    const int row1 = row0 + 8;

    #pragma unroll
    for (int i = 0; i < 8; i++) {
        int li = tid + i * 256;
        int r = li >> 5, c = (li & 31) * 4;
        float4 val = *(const float4*)(q + qbase + (size_t)r * Dc + c);
        uint32_t h, l;
        split2(val.x * scale, val.y * scale, h, l);
        QH[r * QKP + c / 2] = h; QL[r * QKP + c / 2] = l;
        split2(val.z * scale, val.w * scale, h, l);
        QH[r * QKP + c / 2 + 1] = h; QL[r * QKP + c / 2 + 1] = l;
    }

    float oacc[8][4];
    #pragma unroll
    for (int ni = 0; ni < 8; ni++)
        #pragma unroll
        for (int c = 0; c < 4; c++) oacc[ni][c] = 0.f;
    float m0s = -1e30f, m1s = -1e30f, l0s = 0.f, l1s = 0.f;

    for (int kb = 0; kb <= qb; kb++) {
        const size_t kbase = ((size_t)(b * Sc + kb * 64)) * Dc + hh * HDc;
        #pragma unroll
        for (int i = 0; i < 8; i++) {
            int li = tid + i * 256;
            int r = li >> 5, c = (li & 31) * 4;
            float4 kv = *(const float4*)(k + kbase + (size_t)r * Dc + c);
            uint32_t h, l;
            split2(kv.x, kv.y, h, l);
            KH[r * QKP + c / 2] = h; KL[r * QKP + c / 2] = l;
            split2(kv.z, kv.w, h, l);
            KH[r * QKP + c / 2 + 1] = h; KL[r * QKP + c / 2 + 1] = l;
        }
        #pragma unroll
        for (int i = 0; i < 4; i++) {
            int li = tid + i * 256;
            int j = li >> 5, c = (li & 31) * 4;
            float4 v0 = *(const float4*)(v + kbase + (size_t)(2 * j) * Dc + c);
            float4 v1 = *(const float4*)(v + kbase + (size_t)(2 * j + 1) * Dc + c);
            uint32_t h, l;
            uint4 vh, vl;
            split2(v0.x, v1.x, h, l); vh.x = h; vl.x = l;
            split2(v0.y, v1.y, h, l); vh.y = h; vl.y = l;
            split2(v0.z, v1.z, h, l); vh.z = h; vl.z = l;
            split2(v0.w, v1.w, h, l); vh.w = h; vl.w = l;
            *(uint4*)&VH[j * VP + c] = vh;
            *(uint4*)&VL[j * VP + c] = vl;
        }
        __syncthreads();

        float sacc[4][4];
        #pragma unroll
        for (int ni = 0; ni < 4; ni++)
            #pragma unroll
            for (int c = 0; c < 4; c++) sacc[ni][c] = 0.f;

        #pragma unroll
        for (int ks = 0; ks < 8; ks++) {
            int kpb = ks * 8;
            uint32_t ahi[4], alo[4];
            ahi[0] = QH[row0 * QKP + kpb + lm];
            ahi[1] = QH[row1 * QKP + kpb + lm];
            ahi[2] = QH[row0 * QKP + kpb + lm + 4];
            ahi[3] = QH[row1 * QKP + kpb + lm + 4];
            alo[0] = QL[row0 * QKP + kpb + lm];
            alo[1] = QL[row1 * QKP + kpb + lm];
            alo[2] = QL[row0 * QKP + kpb + lm + 4];
            alo[3] = QL[row1 * QKP + kpb + lm + 4];
            #pragma unroll
            for (int ni = 0; ni < 4; ni++) {
                int ck = wx * 32 + ni * 8 + g;
                uint32_t bhi[2], blo[2];
                bhi[0] = KH[ck * QKP + kpb + lm];
                bhi[1] = KH[ck * QKP + kpb + lm + 4];
                blo[0] = KL[ck * QKP + kpb + lm];
                blo[1] = KL[ck * QKP + kpb + lm + 4];
                mma_bf16(sacc[ni], ahi, bhi);
                mma_bf16(sacc[ni], ahi, blo);
                mma_bf16(sacc[ni], alo, bhi);
            }
        }

        if (kb == qb) {
            int qa0 = qb * 64 + row0;
            int qa1 = qb * 64 + row1;
            #pragma unroll
            for (int ni = 0; ni < 4; ni++) {
                int ka = kb * 64 + wx * 32 + ni * 8 + 2 * lm;
                if (ka     > qa0) sacc[ni][0] = -1e30f;
                if (ka + 1 > qa0) sacc[ni][1] = -1e30f;
                if (ka     > qa1) sacc[ni][2] = -1e30f;
                if (ka + 1 > qa1) sacc[ni][3] = -1e30f;
            }
        }

        float rm0 = -1e30f, rm1 = -1e30f;
        #pragma unroll
        for (int ni = 0; ni < 4; ni++) {
            rm0 = fmaxf(rm0, fmaxf(sacc[ni][0], sacc[ni][1]));
            rm1 = fmaxf(rm1, fmaxf(sacc[ni][2], sacc[ni][3]));
        }
        rm0 = fmaxf(rm0, __shfl_xor_sync(0xffffffffu, rm0, 1));
        rm0 = fmaxf(rm0, __shfl_xor_sync(0xffffffffu, rm0, 2));
        rm1 = fmaxf(rm1, __shfl_xor_sync(0xffffffffu, rm1, 1));
        rm1 = fmaxf(rm1, __shfl_xor_sync(0xffffffffu, rm1, 2));
        if (lm == 0) {
            RM[row0 * 2 + wx] = rm0;
            RM[row1 * 2 + wx] = rm1;
        }
        __syncthreads();

        float mn0 = fmaxf(m0s, fmaxf(RM[row0 * 2], RM[row0 * 2 + 1]));
        float mn1 = fmaxf(m1s, fmaxf(RM[row1 * 2], RM[row1 * 2 + 1]));

        float ps0 = 0.f, ps1 = 0.f;
        #pragma unroll
        for (int ni = 0; ni < 4; ni++) {
            float p0 = __expf(sacc[ni][0] - mn0);
            float p1 = __expf(sacc[ni][1] - mn0);
            float p2 = __expf(sacc[ni][2] - mn1);
            float p3 = __expf(sacc[ni][3] - mn1);
            ps0 += p0 + p1; ps1 += p2 + p3;
            int kpw = wx * 16 + ni * 4 + lm;
            uint32_t h, l;
            split2(p0, p1, h, l);
            PH[row0 * PP + kpw] = h; PL[row0 * PP + kpw] = l;
            split2(p2, p3, h, l);
            PH[row1 * PP + kpw] = h; PL[row1 * PP + kpw] = l;
        }
        ps0 += __shfl_xor_sync(0xffffffffu, ps0, 1);
        ps0 += __shfl_xor_sync(0xffffffffu, ps0, 2);
        ps1 += __shfl_xor_sync(0xffffffffu, ps1, 1);
        ps1 += __shfl_xor_sync(0xffffffffu, ps1, 2);
        if (lm == 0) {
            RS[row0 * 2 + wx] = ps0;
            RS[row1 * 2 + wx] = ps1;
        }
        __syncthreads();

        float sc0 = __expf(m0s - mn0);
        float sc1 = __expf(m1s - mn1);
        l0s = l0s * sc0 + RS[row0 * 2] + RS[row0 * 2 + 1];
        l1s = l1s * sc1 + RS[row1 * 2] + RS[row1 * 2 + 1];
        m0s = mn0; m1s = mn1;
        #pragma unroll
        for (int ni = 0; ni < 8; ni++) {
            oacc[ni][0] *= sc0; oacc[ni][1] *= sc0;
            oacc[ni][2] *= sc1; oacc[ni][3] *= sc1;
        }

        #pragma unroll
        for (int ks = 0; ks < 4; ks++) {
            int kpb = ks * 8;
            uint32_t ahi[4], alo[4];
            ahi[0] = PH[row0 * PP + kpb + lm];
            ahi[1] = PH[row1 * PP + kpb + lm];
            ahi[2] = PH[row0 * PP + kpb + lm + 4];
            ahi[3] = PH[row1 * PP + kpb + lm + 4];
            alo[0] = PL[row0 * PP + kpb + lm];
            alo[1] = PL[row1 * PP + kpb + lm];
            alo[2] = PL[row0 * PP + kpb + lm + 4];
            alo[3] = PL[row1 * PP + kpb + lm + 4];
            #pragma unroll
            for (int ni = 0; ni < 8; ni++) {
                int vc = wx * 64 + ni * 8 + g;
                uint32_t bhi[2], blo[2];
                bhi[0] = VH[(kpb + lm)     * VP + vc];
                bhi[1] = VH[(kpb + lm + 4) * VP + vc];
                blo[0] = VL[(kpb + lm)     * VP + vc];
                blo[1] = VL[(kpb + lm + 4) * VP + vc];
                mma_bf16(oacc[ni], ahi, bhi);
                mma_bf16(oacc[ni], ahi, blo);
                mma_bf16(oacc[ni], alo, bhi);
            }
        }
        __syncthreads();
    }

    float inv0 = 1.f / l0s;
    float inv1 = 1.f / l1s;
    #pragma unroll
    for (int ni = 0; ni < 8; ni++) {
        int col = wx * 64 + ni * 8 + 2 * lm;
        *(float2*)&ao[qbase + (size_t)row0 * Dc + col] =
            make_float2(oacc[ni][0] * inv0, oacc[ni][1] * inv0);
        *(float2*)&ao[qbase + (size_t)row1 * Dc + col] =
            make_float2(oacc[ni][2] * inv1, oacc[ni][3] * inv1);
    }
}

__global__ __launch_bounds__(256) void combine_kernel(
    const float* __restrict__ h, const float* __restrict__ moeout,
    float* __restrict__ out)
{
    size_t i = (size_t)blockIdx.x * 256 + threadIdx.x;
    size_t t = i >> 10, d = i & 1023;
    out[i] = h[i] + moeout[(2 * t) * (size_t)Dc + d]
                  + moeout[(2 * t + 1) * (size_t)Dc + d];
}

extern "C" void kernel_launch(void* const* d_in, const int* in_sizes, int n_in,
                              void* d_out, int out_size)
{
    const float* x     = (const float*)d_in[0];
    const float* freqs = (const float*)d_in[1];
    const float* g1    = (const float*)d_in[2];
    const float* b1    = (const float*)d_in[3];
    const float* g2    = (const float*)d_in[4];
    const float* b2    = (const float*)d_in[5];
    const float* Wq    = (const float*)d_in[6];
    const float* Wdkv  = (const float*)d_in[7];
    const float* Wuk   = (const float*)d_in[8];
    const float* Wuv   = (const float*)d_in[9];
    const float* Wo    = (const float*)d_in[10];
    const float* Wg    = (const float*)d_in[11];
    const float* W1    = (const float*)d_in[12];
    const float* W2    = (const float*)d_in[13];
    float* out = (float*)d_out;

    void* bufp = nullptr;
    cudaGetSymbolAddress(&bufp, g_buf);
    float* buf   = (float*)bufp;
    float* xn    = buf + OFF_XN;
    float* qb_   = buf + OFF_Q;
    float* kb_   = buf + OFF_K;
    float* vb_   = buf + OFF_V;
    float* lat   = buf + OFF_LAT;
    float* ao    = buf + OFF_AO;
    float* h     = buf + OFF_H;
    float* hn    = buf + OFF_HN;
    float* act   = buf + OFF_ACT;
    float* moeo  = buf + OFF_MOE;
    float* wslot = buf + OFF_WSLOT;
    int*   elist = (int*)(buf + OFF_ELIST);
    int*   ecnt  = (int*)(buf + OFF_ECNT);

    cudaFuncSetAttribute(flash_tc_kernel,
                         cudaFuncAttributeMaxDynamicSharedMemorySize, FLASH_SMEM);

    reset_kernel<<<1, 32>>>(ecnt);
    ln_kernel<false><<<NT, 256>>>(x, g1, b1, xn,
                                  nullptr, nullptr, nullptr, nullptr);

    // fused Wq (z=0, N=1024) + Wdkv (z=1, N=512)
    tgemm_kernel<0, false><<<dim3(Dc / 128, NT / 128, 2), 256>>>(
        xn, Wq, nullptr, qb_, NT, Dc, Dc, nullptr, nullptr, nullptr, 0, 0,
        Wdkv, lat, Lc);
    // fused Wuk (z=0) + Wuv (z=1), both N=1024
    tgemm_kernel<0, false><<<dim3(Dc / 128, NT / 128, 2), 256>>>(
        lat, Wuk, nullptr, kb_, NT, Lc, Dc, nullptr, nullptr, nullptr, 0, 0,
        Wuv, vb_, Dc);

    rope_kernel<<<(NT * (Dc / 2)) / 256, 256>>>(qb_, kb_, freqs);

    flash_tc_kernel<<<dim3(Sc / 64, Hc, Bc), 256, FLASH_SMEM>>>(qb_, kb_, vb_, ao);

    tgemm_kernel<1, false><<<dim3(Dc / 128, NT / 128), 256>>>(
        ao, Wo, x, h, NT, Dc, Dc, nullptr, nullptr, nullptr, 0, 0,
        nullptr, nullptr, 0);

    // second LN with fused gate
    ln_kernel<true><<<NT, 256>>>(h, g2, b2, hn, Wg, wslot, elist, ecnt);

    tgemm_kernel<2, true><<<dim3(Fc / 128, NT / 128, Ec), 256>>>(
        hn, W1, nullptr, act, 0, Dc, Fc, elist, ecnt, nullptr, 1, (size_t)Dc * Fc,
        nullptr, nullptr, 0);
    tgemm_kernel<3, true><<<dim3(Dc / 128, NT / 128, Ec), 256>>>(
        act, W2, nullptr, moeo, 0, Fc, Dc, elist, ecnt, wslot, 0, (size_t)Fc * Dc,
        nullptr, nullptr, 0);

    combine_kernel<<<(NT * Dc) / 256, 256>>>(h, moeo, out);
}